// round 13
// baseline (speedup 1.0000x reference)
#include <cuda_runtime.h>
#include <cuda_fp16.h>
#include <cstdint>

#define NN 100000
#define NE 3200000
#define NH 64

// ---------------- scratch (__device__ globals: allocation-free) ----------------
__device__ int    g_cnt[NN];
__device__ int    g_partial[512];
__device__ int    g_rowptr[NN + 1];
__device__ int    g_cursor[NN];
__device__ float  g_dis[NN];
__device__ int    g_esrc[NE];             // CSR-by-dst src indices (weights separable)
__device__ float  g_xr[(size_t)NN * 128]; // tf32-rounded copy of x (GEMM A operand)
__device__ float  g_C[(size_t)NN * 448];  // fused GEMM output: c_0..c_5 | skip
__device__ float  g_b0[NN * NH];
__device__ float  g_b1[NN * NH];
__device__ float  g_b2[NN * NH];
__device__ __half g_H0[NN * NH];          // pre-scaled (dis⊙) fp16 gather buffers
__device__ __half g_H1[NN * NH];
__device__ __half g_H2[NN * NH];
__device__ __half g_H3[NN * NH];
__device__ float  g_h1[NN * NH];
__device__ float  g_h2[NN * NH];
// tf32 transposed weights (rows = output col, contiguous K) + fused bias vectors
__device__ float g_Wt0[448 * 128];
__device__ float g_Wt1[448 * 64];
__device__ float g_Wt2[448 * 64];
__device__ float g_Wtm[64 * 192];
__device__ float g_bias0[448];
__device__ float g_bias1[448];
__device__ float g_bias2[448];
__device__ float g_biasm[64];

__device__ __forceinline__ float to_tf32(float v) {
    uint32_t u;
    asm("cvt.rna.tf32.f32 %0, %1;" : "=r"(u) : "f"(v));
    return __uint_as_float(u);
}

__device__ __forceinline__ void mma_m16n8k8(float* c, uint32_t a0, uint32_t a1,
                                            uint32_t a2, uint32_t a3,
                                            uint32_t b0, uint32_t b1) {
    asm volatile(
        "mma.sync.aligned.m16n8k8.row.col.f32.tf32.tf32.f32 "
        "{%0,%1,%2,%3}, {%4,%5,%6,%7}, {%8,%9}, {%0,%1,%2,%3};"
        : "+f"(c[0]), "+f"(c[1]), "+f"(c[2]), "+f"(c[3])
        : "r"(a0), "r"(a1), "r"(a2), "r"(a3), "r"(b0), "r"(b1));
}

__device__ __forceinline__ void cp_async16(uint32_t saddr, const void* gptr, bool pred) {
    int sz = pred ? 16 : 0;
    asm volatile("cp.async.cg.shared.global [%0], [%1], 16, %2;\n"
                 :: "r"(saddr), "l"(gptr), "r"(sz));
}
#define CP_COMMIT() asm volatile("cp.async.commit_group;\n" ::: "memory")

// ---------------- graph preprocessing ----------------
__global__ void hist_kernel(const int* __restrict__ dst, int* __restrict__ cnt, int E) {
    int i = blockIdx.x * blockDim.x + threadIdx.x;
    if (i < E) atomicAdd(&cnt[dst[i]], 1);
}

__global__ void reduce_kernel(const int* __restrict__ cnt, int* __restrict__ partial, int n) {
    __shared__ int s[8];
    int i = blockIdx.x * 256 + threadIdx.x;
    int v = (i < n) ? cnt[i] : 0;
    #pragma unroll
    for (int o = 16; o; o >>= 1) v += __shfl_down_sync(0xffffffffu, v, o);
    if ((threadIdx.x & 31) == 0) s[threadIdx.x >> 5] = v;
    __syncthreads();
    if (threadIdx.x < 8) {
        int t = s[threadIdx.x];
        #pragma unroll
        for (int o = 4; o; o >>= 1) t += __shfl_down_sync(0xffu, t, o);
        if (threadIdx.x == 0) partial[blockIdx.x] = t;
    }
}

__global__ void scanp_kernel(int* __restrict__ partial, int nb, int* __restrict__ total_out) {
    __shared__ int ws[16];
    int tid = threadIdx.x, lane = tid & 31, w = tid >> 5;
    int v = (tid < nb) ? partial[tid] : 0;
    int x = v;
    #pragma unroll
    for (int o = 1; o < 32; o <<= 1) {
        int y = __shfl_up_sync(0xffffffffu, x, o);
        if (lane >= o) x += y;
    }
    if (lane == 31) ws[w] = x;
    __syncthreads();
    if (w == 0 && lane < 16) {
        int t = ws[lane];
        #pragma unroll
        for (int o = 1; o < 16; o <<= 1) {
            int y = __shfl_up_sync(0xffffu, t, o);
            if (lane >= o) t += y;
        }
        ws[lane] = t;
    }
    __syncthreads();
    int excl = x - v + (w ? ws[w - 1] : 0);
    if (tid < nb) partial[tid] = excl;
    if (tid == nb - 1) total_out[0] = excl + v;
}

// block-scan apply + fused dis = rsqrt(deg)
__global__ void apply_kernel(const int* __restrict__ cnt, const int* __restrict__ partial,
                             int* __restrict__ rowptr, int* __restrict__ cursor,
                             float* __restrict__ dis, int n) {
    __shared__ int ws[8];
    int i = blockIdx.x * 256 + threadIdx.x;
    int lane = threadIdx.x & 31, w = threadIdx.x >> 5;
    int v = (i < n) ? cnt[i] : 0;
    int x = v;
    #pragma unroll
    for (int o = 1; o < 32; o <<= 1) {
        int y = __shfl_up_sync(0xffffffffu, x, o);
        if (lane >= o) x += y;
    }
    if (lane == 31) ws[w] = x;
    __syncthreads();
    if (w == 0 && lane < 8) {
        int t = ws[lane];
        #pragma unroll
        for (int o = 1; o < 8; o <<= 1) {
            int y = __shfl_up_sync(0xffu, t, o);
            if (lane >= o) t += y;
        }
        ws[lane] = t;
    }
    __syncthreads();
    int excl = x - v + (w ? ws[w - 1] : 0) + partial[blockIdx.x];
    if (i < n) {
        rowptr[i] = excl;
        cursor[i] = excl;
        dis[i] = v > 0 ? rsqrtf((float)v) : 0.0f;
    }
}

__global__ void fill_kernel(const int* __restrict__ src, const int* __restrict__ dst,
                            int* __restrict__ cursor, int* __restrict__ esrc, int E) {
    int i = blockIdx.x * blockDim.x + threadIdx.x;
    if (i < E) {
        int d = dst[i];
        int pos = atomicAdd(&cursor[d], 1);
        esrc[pos] = src[i];
    }
}

// ---------------- weight prep (+ x rounding + cnt zeroing fused) ----------------
__global__ void prep_weights(const float* __restrict__ W0, const float* __restrict__ Ws0,
                             const float* __restrict__ W1, const float* __restrict__ Ws1,
                             const float* __restrict__ W2, const float* __restrict__ Ws2,
                             const float* __restrict__ Wm,
                             const float* __restrict__ b0, const float* __restrict__ bs0,
                             const float* __restrict__ b1, const float* __restrict__ bs1,
                             const float* __restrict__ b2, const float* __restrict__ bs2,
                             const float* __restrict__ bm,
                             const float* __restrict__ x, float* __restrict__ xr,
                             int* __restrict__ cnt,
                             float* __restrict__ Wt0, float* __restrict__ Wt1,
                             float* __restrict__ Wt2, float* __restrict__ Wtm,
                             float* __restrict__ bias0, float* __restrict__ bias1,
                             float* __restrict__ bias2, float* __restrict__ biasm) {
    int idx = blockIdx.x * blockDim.x + threadIdx.x;
    const int SX = NN * 32;  // x as float4 elements
    const int SZ = NN;       // cnt zeroing
    const int S0 = 448 * 128, S1 = 448 * 64, S2 = 448 * 64, SM = 64 * 192;
    if (idx < SX) {
        float4 v = ((const float4*)x)[idx];
        v.x = to_tf32(v.x); v.y = to_tf32(v.y); v.z = to_tf32(v.z); v.w = to_tf32(v.w);
        ((float4*)xr)[idx] = v;
        return;
    }
    idx -= SX;
    if (idx < SZ) { cnt[idx] = 0; return; }
    idx -= SZ;
    if (idx < S0) {
        int n = idx / 128, k = idx % 128;
        float v = (n < 384) ? W0[(size_t)(n / 64) * 128 * 64 + (size_t)k * 64 + (n % 64)]
                            : Ws0[(size_t)k * 64 + (n - 384)];
        Wt0[idx] = to_tf32(v);
        return;
    }
    idx -= S0;
    if (idx < S1) {
        int n = idx / 64, k = idx % 64;
        float v = (n < 384) ? W1[(size_t)(n / 64) * 64 * 64 + (size_t)k * 64 + (n % 64)]
                            : Ws1[(size_t)k * 64 + (n - 384)];
        Wt1[idx] = to_tf32(v);
        return;
    }
    idx -= S1;
    if (idx < S2) {
        int n = idx / 64, k = idx % 64;
        float v = (n < 384) ? W2[(size_t)(n / 64) * 64 * 64 + (size_t)k * 64 + (n % 64)]
                            : Ws2[(size_t)k * 64 + (n - 384)];
        Wt2[idx] = to_tf32(v);
        return;
    }
    idx -= S2;
    if (idx < SM) {
        int n = idx / 192, k = idx % 192;
        float v = (n < 32) ? Wm[(size_t)k * 32 + n]
                           : Wm[(size_t)192 * 32 + (size_t)k * 32 + (n - 32)];
        Wtm[idx] = to_tf32(v);
        return;
    }
    idx -= SM;
    if (idx < 448) { bias0[idx] = (idx < 64) ? b0[idx] : (idx >= 384 ? bs0[idx - 384] : 0.f); return; }
    idx -= 448;
    if (idx < 448) { bias1[idx] = (idx < 64) ? b1[idx] : (idx >= 384 ? bs1[idx - 384] : 0.f); return; }
    idx -= 448;
    if (idx < 448) { bias2[idx] = (idx < 64) ? b2[idx] : (idx >= 384 ? bs2[idx - 384] : 0.f); return; }
    idx -= 448;
    if (idx < 64) { biasm[idx] = (idx < 32) ? bm[idx] : 0.f; return; }
}

// ---------------- mma.sync tf32 GEMM (cp.async 2-stage double buffer) ----------------
// A operands MUST be pre-rounded to tf32 (values pass through cp.async untouched).
template<int KD, int SPLIT, int WLO, int WHI>
__global__ __launch_bounds__(256)
void gemm_mma(const float* __restrict__ A, const float* __restrict__ A2,
              const float* __restrict__ Wt, const float* __restrict__ biasfull,
              const float* __restrict__ dis, __half* __restrict__ Hout,
              float* __restrict__ C, int OUT, int N) {
    constexpr int BM = 128, BN = 64, LDA = 36;
    constexpr int NKT = KD / 32;
    constexpr int A2S = (KD > SPLIT) ? (KD - SPLIT) : 1;
    __shared__ float As[2][BM * LDA];
    __shared__ float Bs[2][BN * LDA];

    int tid = threadIdx.x;
    int lane = tid & 31, wid = tid >> 5;
    int wm = wid & 3, wn = wid >> 2;
    int quad = lane >> 2, qt = lane & 3;
    int br = blockIdx.x * BM;
    int colbase = blockIdx.y * BN;

    float acc[2][4][4];
    #pragma unroll
    for (int mi = 0; mi < 2; mi++)
        #pragma unroll
        for (int ni = 0; ni < 4; ni++)
            #pragma unroll
            for (int j = 0; j < 4; j++) acc[mi][ni][j] = 0.f;

    int ar[4], ac4[4], bn_[2], bc4[2];
    #pragma unroll
    for (int t = 0; t < 4; t++) {
        int i4 = tid + 256 * t;
        ar[t] = i4 >> 3; ac4[t] = i4 & 7;
    }
    #pragma unroll
    for (int t = 0; t < 2; t++) {
        int i4 = tid + 256 * t;
        bn_[t] = i4 >> 3; bc4[t] = i4 & 7;
    }

    uint32_t sA[2], sB[2];
    sA[0] = (uint32_t)__cvta_generic_to_shared(As[0]);
    sA[1] = (uint32_t)__cvta_generic_to_shared(As[1]);
    sB[0] = (uint32_t)__cvta_generic_to_shared(Bs[0]);
    sB[1] = (uint32_t)__cvta_generic_to_shared(Bs[1]);

    auto issue = [&](int kt, int s) {
        int k0 = kt * 32;
        #pragma unroll
        for (int t = 0; t < 4; t++) {
            int gr = br + ar[t];
            int col = k0 + ac4[t] * 4;
            const float* src;
            if (SPLIT == KD || col < SPLIT) src = A + (size_t)gr * SPLIT + col;
            else                            src = A2 + (size_t)gr * A2S + (col - SPLIT);
            cp_async16(sA[s] + (ar[t] * LDA + ac4[t] * 4) * 4, src, gr < N);
        }
        #pragma unroll
        for (int t = 0; t < 2; t++)
            cp_async16(sB[s] + (bn_[t] * LDA + bc4[t] * 4) * 4,
                       Wt + (size_t)(colbase + bn_[t]) * KD + k0 + bc4[t] * 4, true);
        CP_COMMIT();
    };

    issue(0, 0);
    #pragma unroll
    for (int kt = 0; kt < NKT; kt++) {
        int s = kt & 1;
        if (kt + 1 < NKT) {
            issue(kt + 1, (kt + 1) & 1);
            asm volatile("cp.async.wait_group 1;\n" ::: "memory");
        } else {
            asm volatile("cp.async.wait_group 0;\n" ::: "memory");
        }
        __syncthreads();
        const uint32_t* Asu = (const uint32_t*)As[s];
        const uint32_t* Bsu = (const uint32_t*)Bs[s];
        #pragma unroll
        for (int ks = 0; ks < 4; ks++) {
            int kk = ks * 8;
            uint32_t a[2][4];
            #pragma unroll
            for (int mi = 0; mi < 2; mi++) {
                int row = wm * 32 + mi * 16 + quad;
                a[mi][0] = Asu[row * LDA + kk + qt];
                a[mi][1] = Asu[(row + 8) * LDA + kk + qt];
                a[mi][2] = Asu[row * LDA + kk + qt + 4];
                a[mi][3] = Asu[(row + 8) * LDA + kk + qt + 4];
            }
            #pragma unroll
            for (int ni = 0; ni < 4; ni++) {
                int col = wn * 32 + ni * 8 + quad;
                uint32_t b0 = Bsu[col * LDA + kk + qt];
                uint32_t b1 = Bsu[col * LDA + kk + qt + 4];
                #pragma unroll
                for (int mi = 0; mi < 2; mi++)
                    mma_m16n8k8(acc[mi][ni], a[mi][0], a[mi][1], a[mi][2], a[mi][3], b0, b1);
            }
        }
        __syncthreads();
    }
    #pragma unroll
    for (int mi = 0; mi < 2; mi++) {
        int r0 = br + wm * 32 + mi * 16 + quad;
        float d0 = 0.f, d1 = 0.f;
        if (WHI > WLO) {
            if (r0 < N) d0 = __ldg(dis + r0);
            if (r0 + 8 < N) d1 = __ldg(dis + r0 + 8);
        }
        #pragma unroll
        for (int ni = 0; ni < 4; ni++) {
            int cg = colbase + wn * 32 + ni * 8 + qt * 2;
            float bx = __ldg(biasfull + cg), by = __ldg(biasfull + cg + 1);
            float v0x = acc[mi][ni][0] + bx, v0y = acc[mi][ni][1] + by;
            float v1x = acc[mi][ni][2] + bx, v1y = acc[mi][ni][3] + by;
            bool inw = (WHI > WLO) && cg >= WLO && cg < WHI;
            if (r0 < N) {
                *(float2*)(C + (size_t)r0 * OUT + cg) = make_float2(v0x, v0y);
                if (inw)
                    ((__half2*)Hout)[(size_t)r0 * ((WHI - WLO) / 2) + (cg - WLO) / 2] =
                        __floats2half2_rn(d0 * v0x, d0 * v0y);
            }
            if (r0 + 8 < N) {
                *(float2*)(C + (size_t)(r0 + 8) * OUT + cg) = make_float2(v1x, v1y);
                if (inw)
                    ((__half2*)Hout)[(size_t)(r0 + 8) * ((WHI - WLO) / 2) + (cg - WLO) / 2] =
                        __floats2half2_rn(d1 * v1x, d1 * v1y);
            }
        }
    }
}

// ---------------- Clenshaw propagation (vectorized int4 index broadcasts) ----------------
template<int F>
__global__ __launch_bounds__(256)
void clenshaw_prop(const int* __restrict__ rowptr, const int* __restrict__ esrc,
                   const __half* __restrict__ tin_h,
                   const float* __restrict__ add, int add_stride,
                   const float* __restrict__ sub, int sub_stride,
                   const float* __restrict__ skip, int skip_stride,
                   const float* __restrict__ dis,
                   float* __restrict__ out, int out_stride,
                   __half* __restrict__ outh,
                   float scale, int do_relu, int tf32_out, int n) {
    constexpr int L = F / 2;
    int gt = blockIdx.x * blockDim.x + threadIdx.x;
    int node = gt / L;
    if (node >= n) return;
    int sl = gt & (L - 1);
    int beg = __ldg(rowptr + node), end = __ldg(rowptr + node + 1);
    const __half2* tin2 = (const __half2*)tin_h;
    float2 a0 = make_float2(0.f, 0.f), a1 = make_float2(0.f, 0.f);
    float2 a2 = make_float2(0.f, 0.f), a3 = make_float2(0.f, 0.f);
    int p = beg;
    // prologue: advance to 4-aligned index so int4 loads of esrc are legal
    for (; p < end && (p & 3); ++p) {
        int s = __ldg(esrc + p);
        float2 f = __half22float2(__ldg(tin2 + (size_t)s * L + sl));
        a0.x += f.x; a0.y += f.y;
    }
    // main loop: 8 edges per iter; indices via 2 broadcast LDG.128
    for (; p + 8 <= end; p += 8) {
        int4 ia = __ldg((const int4*)(esrc + p));
        int4 ib = __ldg((const int4*)(esrc + p + 4));
        float2 f0 = __half22float2(__ldg(tin2 + (size_t)ia.x * L + sl));
        float2 f1 = __half22float2(__ldg(tin2 + (size_t)ia.y * L + sl));
        float2 f2 = __half22float2(__ldg(tin2 + (size_t)ia.z * L + sl));
        float2 f3 = __half22float2(__ldg(tin2 + (size_t)ia.w * L + sl));
        float2 f4 = __half22float2(__ldg(tin2 + (size_t)ib.x * L + sl));
        float2 f5 = __half22float2(__ldg(tin2 + (size_t)ib.y * L + sl));
        float2 f6 = __half22float2(__ldg(tin2 + (size_t)ib.z * L + sl));
        float2 f7 = __half22float2(__ldg(tin2 + (size_t)ib.w * L + sl));
        a0.x += f0.x + f4.x; a0.y += f0.y + f4.y;
        a1.x += f1.x + f5.x; a1.y += f1.y + f5.y;
        a2.x += f2.x + f6.x; a2.y += f2.y + f6.y;
        a3.x += f3.x + f7.x; a3.y += f3.y + f7.y;
    }
    // 4-edge step (one more int4 broadcast) then scalar tail
    if (p + 4 <= end) {
        int4 ia = __ldg((const int4*)(esrc + p));
        float2 f0 = __half22float2(__ldg(tin2 + (size_t)ia.x * L + sl));
        float2 f1 = __half22float2(__ldg(tin2 + (size_t)ia.y * L + sl));
        float2 f2 = __half22float2(__ldg(tin2 + (size_t)ia.z * L + sl));
        float2 f3 = __half22float2(__ldg(tin2 + (size_t)ia.w * L + sl));
        a0.x += f0.x; a0.y += f0.y;
        a1.x += f1.x; a1.y += f1.y;
        a2.x += f2.x; a2.y += f2.y;
        a3.x += f3.x; a3.y += f3.y;
        p += 4;
    }
    for (; p < end; ++p) {
        int s = __ldg(esrc + p);
        float2 f = __half22float2(__ldg(tin2 + (size_t)s * L + sl));
        a0.x += f.x; a0.y += f.y;
    }
    float d = __ldg(dis + node);
    float sd = scale * d;
    float vx = sd * ((a0.x + a1.x) + (a2.x + a3.x));
    float vy = sd * ((a0.y + a1.y) + (a2.y + a3.y));
    float2 ad = ((const float2*)(add + (size_t)node * add_stride))[sl];
    vx += ad.x; vy += ad.y;
    if (sub) {
        float2 s = ((const float2*)(sub + (size_t)node * sub_stride))[sl];
        vx -= s.x; vy -= s.y;
    }
    if (do_relu) { vx = fmaxf(vx, 0.f); vy = fmaxf(vy, 0.f); }
    if (skip) {
        float2 s = ((const float2*)(skip + (size_t)node * skip_stride))[sl];
        vx += s.x; vy += s.y;
    }
    float wx = tf32_out ? to_tf32(vx) : vx;
    float wy = tf32_out ? to_tf32(vy) : vy;
    ((float2*)(out + (size_t)node * out_stride))[sl] = make_float2(wx, wy);
    if (outh)
        ((__half2*)outh)[(size_t)node * L + sl] = __floats2half2_rn(d * vx, d * vy);
}

// ---------------- host orchestration ----------------
static void prop64(const int* rowptr, const int* esrc, const __half* tin_h,
                   const float* add, int as, const float* sub, int ss,
                   const float* skip, int ks, const float* dis,
                   float* out, int os, __half* outh, float scale, int relu, int tf32o) {
    int blocks = (NN * 32 + 255) / 256;
    clenshaw_prop<64><<<blocks, 256>>>(rowptr, esrc, tin_h, add, as, sub, ss,
                                       skip, ks, dis, out, os, outh, scale, relu, tf32o, NN);
}

static void cheb_layer(const float* h, int kd,
                       const float* Wt, const float* biasfull,
                       float* hout, const int* rowptr, const int* esrc,
                       const float* dis,
                       float* C, float* B0, float* B1, float* B2,
                       __half* H0, __half* H1, __half* H2, __half* H3) {
    dim3 grid((NN + 127) / 128, 7);
    if (kd == 128)
        gemm_mma<128, 128, 320, 384><<<grid, 256>>>(h, nullptr, Wt, biasfull, dis, H3, C, 448, NN);
    else
        gemm_mma<64, 64, 320, 384><<<grid, 256>>>(h, nullptr, Wt, biasfull, dis, H3, C, 448, NN);
    prop64(rowptr, esrc, H3, C + 4 * 64, 448, nullptr, 0, nullptr, 0, dis, B0, 64, H0, -2.f, 0, 0);
    prop64(rowptr, esrc, H0, C + 3 * 64, 448, C + 5 * 64, 448, nullptr, 0, dis, B1, 64, H1, -2.f, 0, 0);
    prop64(rowptr, esrc, H1, C + 2 * 64, 448, B0, 64, nullptr, 0, dis, B2, 64, H2, -2.f, 0, 0);
    prop64(rowptr, esrc, H2, C + 1 * 64, 448, B1, 64, nullptr, 0, dis, B0, 64, H0, -2.f, 0, 0);
    // hout feeds only the next GEMM -> store tf32-rounded (preserves cvt.rna GEMM semantics)
    prop64(rowptr, esrc, H0, C, 448, B2, 64, C + 6 * 64, 448, dis, hout, 64, nullptr, -1.f, 1, 1);
}

extern "C" void kernel_launch(void* const* d_in, const int* in_sizes, int n_in,
                              void* d_out, int out_size) {
    const float* x   = (const float*)d_in[0];
    const int*   ei  = (const int*)d_in[1];
    const float* W0  = (const float*)d_in[2];
    const float* b0  = (const float*)d_in[3];
    const float* Ws0 = (const float*)d_in[4];
    const float* bs0 = (const float*)d_in[5];
    const float* W1  = (const float*)d_in[6];
    const float* b1  = (const float*)d_in[7];
    const float* Ws1 = (const float*)d_in[8];
    const float* bs1 = (const float*)d_in[9];
    const float* W2  = (const float*)d_in[10];
    const float* b2  = (const float*)d_in[11];
    const float* Ws2 = (const float*)d_in[12];
    const float* bs2 = (const float*)d_in[13];
    const float* Wm  = (const float*)d_in[14];
    const float* bm  = (const float*)d_in[15];
    float* out = (float*)d_out;

    const int* src = ei;
    const int* dst = ei + NE;

    void* p;
    cudaGetSymbolAddress(&p, g_cnt);     int*    cnt     = (int*)p;
    cudaGetSymbolAddress(&p, g_partial); int*    partial = (int*)p;
    cudaGetSymbolAddress(&p, g_rowptr);  int*    rowptr  = (int*)p;
    cudaGetSymbolAddress(&p, g_cursor);  int*    cursor  = (int*)p;
    cudaGetSymbolAddress(&p, g_dis);     float*  dis     = (float*)p;
    cudaGetSymbolAddress(&p, g_esrc);    int*    esrc    = (int*)p;
    cudaGetSymbolAddress(&p, g_xr);      float*  xr      = (float*)p;
    cudaGetSymbolAddress(&p, g_C);       float*  C       = (float*)p;
    cudaGetSymbolAddress(&p, g_b0);      float*  B0      = (float*)p;
    cudaGetSymbolAddress(&p, g_b1);      float*  B1      = (float*)p;
    cudaGetSymbolAddress(&p, g_b2);      float*  B2      = (float*)p;
    cudaGetSymbolAddress(&p, g_H0);      __half* H0      = (__half*)p;
    cudaGetSymbolAddress(&p, g_H1);      __half* H1      = (__half*)p;
    cudaGetSymbolAddress(&p, g_H2);      __half* H2      = (__half*)p;
    cudaGetSymbolAddress(&p, g_H3);      __half* H3      = (__half*)p;
    cudaGetSymbolAddress(&p, g_h1);      float*  h1      = (float*)p;
    cudaGetSymbolAddress(&p, g_h2);      float*  h2      = (float*)p;
    cudaGetSymbolAddress(&p, g_Wt0);     float*  Wt0     = (float*)p;
    cudaGetSymbolAddress(&p, g_Wt1);     float*  Wt1     = (float*)p;
    cudaGetSymbolAddress(&p, g_Wt2);     float*  Wt2     = (float*)p;
    cudaGetSymbolAddress(&p, g_Wtm);     float*  Wtm     = (float*)p;
    cudaGetSymbolAddress(&p, g_bias0);   float*  bias0   = (float*)p;
    cudaGetSymbolAddress(&p, g_bias1);   float*  bias1   = (float*)p;
    cudaGetSymbolAddress(&p, g_bias2);   float*  bias2   = (float*)p;
    cudaGetSymbolAddress(&p, g_biasm);   float*  biasm   = (float*)p;

    // ---- weight prep + x rounding + cnt zeroing (single launch) ----
    {
        int total = NN * 32 + NN + 448 * 128 + 448 * 64 + 448 * 64 + 64 * 192 + 448 * 3 + 64;
        prep_weights<<<(total + 255) / 256, 256>>>(W0, Ws0, W1, Ws1, W2, Ws2, Wm,
                                                   b0, bs0, b1, bs1, b2, bs2, bm,
                                                   x, xr, cnt,
                                                   Wt0, Wt1, Wt2, Wtm,
                                                   bias0, bias1, bias2, biasm);
    }

    // ---- preprocessing: degree + dis, CSR (sorted by dst) ----
    hist_kernel<<<(NE + 255) / 256, 256>>>(dst, cnt, NE);
    int nb = (NN + 255) / 256;
    reduce_kernel<<<nb, 256>>>(cnt, partial, NN);
    scanp_kernel<<<1, 512>>>(partial, nb, rowptr + NN);
    apply_kernel<<<nb, 256>>>(cnt, partial, rowptr, cursor, dis, NN);
    fill_kernel<<<(NE + 255) / 256, 256>>>(src, dst, cursor, esrc, NE);

    // ---- 3 Kipf blocks (Clenshaw, separable-weight fp16 gather) ----
    cheb_layer(xr,  128, Wt0, bias0, h1, rowptr, esrc, dis, C, B0, B1, B2, H0, H1, H2, H3);
    cheb_layer(h1,   64, Wt1, bias1, h2, rowptr, esrc, dis, C, B0, B1, B2, H0, H1, H2, H3);
    cheb_layer(h2,   64, Wt2, bias2, h1, rowptr, esrc, dis, C, B0, B1, B2, H0, H1, H2, H3);

    // ---- mix head: dual-source GEMM (h1 | xr) -> ChebConv K=2 -> out ----
    {
        dim3 grid((NN + 127) / 128, 1);
        gemm_mma<192, 64, 32, 64><<<grid, 256>>>(h1, xr, Wtm, biasm, dis, H0, B0, 64, NN);
        int blocks = (NN * 16 + 255) / 256;
        clenshaw_prop<32><<<blocks, 256>>>(rowptr, esrc, H0, B0, 64, nullptr, 0,
                                           nullptr, 0, dis, out, 32, nullptr, -1.f, 0, 0, NN);
    }
}

// round 14
// speedup vs baseline: 1.0181x; 1.0181x over previous
#include <cuda_runtime.h>
#include <cuda_fp16.h>
#include <cstdint>

#define NN 100000
#define NE 3200000
#define NH 64

// ---------------- scratch (__device__ globals: allocation-free) ----------------
__device__ int    g_cnt[NN];
__device__ int    g_partial[512];
__device__ int    g_rowptr[NN + 1];
__device__ int    g_cursor[NN];
__device__ float  g_dis[NN];
__device__ int    g_esrc[NE];             // CSR-by-dst src indices (weights separable)
__device__ float  g_xr[(size_t)NN * 128]; // tf32-rounded copy of x (GEMM A operand)
__device__ float  g_C[(size_t)NN * 448];  // fused GEMM output: c_0..c_5 | skip
__device__ __half g_H0[NN * NH];          // pre-scaled (dis⊙) fp16 gather buffers
__device__ __half g_H1[NN * NH];
__device__ __half g_H2[NN * NH];
__device__ __half g_H3[NN * NH];
__device__ __half g_S0[NN * NH];          // fp16 Clenshaw b_k value buffers (sub operands)
__device__ __half g_S1[NN * NH];
__device__ __half g_S2[NN * NH];
__device__ float  g_h1[NN * NH];
__device__ float  g_h2[NN * NH];
// tf32 transposed weights (rows = output col, contiguous K) + fused bias vectors
__device__ float g_Wt0[448 * 128];
__device__ float g_Wt1[448 * 64];
__device__ float g_Wt2[448 * 64];
__device__ float g_Wtm[64 * 192];
__device__ float g_bias0[448];
__device__ float g_bias1[448];
__device__ float g_bias2[448];
__device__ float g_biasm[64];

__device__ __forceinline__ float to_tf32(float v) {
    uint32_t u;
    asm("cvt.rna.tf32.f32 %0, %1;" : "=r"(u) : "f"(v));
    return __uint_as_float(u);
}

__device__ __forceinline__ void mma_m16n8k8(float* c, uint32_t a0, uint32_t a1,
                                            uint32_t a2, uint32_t a3,
                                            uint32_t b0, uint32_t b1) {
    asm volatile(
        "mma.sync.aligned.m16n8k8.row.col.f32.tf32.tf32.f32 "
        "{%0,%1,%2,%3}, {%4,%5,%6,%7}, {%8,%9}, {%0,%1,%2,%3};"
        : "+f"(c[0]), "+f"(c[1]), "+f"(c[2]), "+f"(c[3])
        : "r"(a0), "r"(a1), "r"(a2), "r"(a3), "r"(b0), "r"(b1));
}

__device__ __forceinline__ void cp_async16(uint32_t saddr, const void* gptr, bool pred) {
    int sz = pred ? 16 : 0;
    asm volatile("cp.async.cg.shared.global [%0], [%1], 16, %2;\n"
                 :: "r"(saddr), "l"(gptr), "r"(sz));
}
#define CP_COMMIT() asm volatile("cp.async.commit_group;\n" ::: "memory")

// ---------------- graph preprocessing ----------------
__global__ void hist_kernel(const int* __restrict__ dst, int* __restrict__ cnt, int E) {
    int i = blockIdx.x * blockDim.x + threadIdx.x;
    if (i < E) atomicAdd(&cnt[dst[i]], 1);
}

__global__ void reduce_kernel(const int* __restrict__ cnt, int* __restrict__ partial, int n) {
    __shared__ int s[8];
    int i = blockIdx.x * 256 + threadIdx.x;
    int v = (i < n) ? cnt[i] : 0;
    #pragma unroll
    for (int o = 16; o; o >>= 1) v += __shfl_down_sync(0xffffffffu, v, o);
    if ((threadIdx.x & 31) == 0) s[threadIdx.x >> 5] = v;
    __syncthreads();
    if (threadIdx.x < 8) {
        int t = s[threadIdx.x];
        #pragma unroll
        for (int o = 4; o; o >>= 1) t += __shfl_down_sync(0xffu, t, o);
        if (threadIdx.x == 0) partial[blockIdx.x] = t;
    }
}

__global__ void scanp_kernel(int* __restrict__ partial, int nb, int* __restrict__ total_out) {
    __shared__ int ws[16];
    int tid = threadIdx.x, lane = tid & 31, w = tid >> 5;
    int v = (tid < nb) ? partial[tid] : 0;
    int x = v;
    #pragma unroll
    for (int o = 1; o < 32; o <<= 1) {
        int y = __shfl_up_sync(0xffffffffu, x, o);
        if (lane >= o) x += y;
    }
    if (lane == 31) ws[w] = x;
    __syncthreads();
    if (w == 0 && lane < 16) {
        int t = ws[lane];
        #pragma unroll
        for (int o = 1; o < 16; o <<= 1) {
            int y = __shfl_up_sync(0xffffu, t, o);
            if (lane >= o) t += y;
        }
        ws[lane] = t;
    }
    __syncthreads();
    int excl = x - v + (w ? ws[w - 1] : 0);
    if (tid < nb) partial[tid] = excl;
    if (tid == nb - 1) total_out[0] = excl + v;
}

// block-scan apply + fused dis = rsqrt(deg)
__global__ void apply_kernel(const int* __restrict__ cnt, const int* __restrict__ partial,
                             int* __restrict__ rowptr, int* __restrict__ cursor,
                             float* __restrict__ dis, int n) {
    __shared__ int ws[8];
    int i = blockIdx.x * 256 + threadIdx.x;
    int lane = threadIdx.x & 31, w = threadIdx.x >> 5;
    int v = (i < n) ? cnt[i] : 0;
    int x = v;
    #pragma unroll
    for (int o = 1; o < 32; o <<= 1) {
        int y = __shfl_up_sync(0xffffffffu, x, o);
        if (lane >= o) x += y;
    }
    if (lane == 31) ws[w] = x;
    __syncthreads();
    if (w == 0 && lane < 8) {
        int t = ws[lane];
        #pragma unroll
        for (int o = 1; o < 8; o <<= 1) {
            int y = __shfl_up_sync(0xffu, t, o);
            if (lane >= o) t += y;
        }
        ws[lane] = t;
    }
    __syncthreads();
    int excl = x - v + (w ? ws[w - 1] : 0) + partial[blockIdx.x];
    if (i < n) {
        rowptr[i] = excl;
        cursor[i] = excl;
        dis[i] = v > 0 ? rsqrtf((float)v) : 0.0f;
    }
}

__global__ void fill_kernel(const int* __restrict__ src, const int* __restrict__ dst,
                            int* __restrict__ cursor, int* __restrict__ esrc, int E) {
    int i = blockIdx.x * blockDim.x + threadIdx.x;
    if (i < E) {
        int d = dst[i];
        int pos = atomicAdd(&cursor[d], 1);
        esrc[pos] = src[i];
    }
}

// round x to tf32 once (preserves cvt.rna semantics for cp.async GEMM path)
__global__ void round_x(const float* __restrict__ x, float* __restrict__ xr, int total4) {
    int i = blockIdx.x * blockDim.x + threadIdx.x;
    if (i < total4) {
        float4 v = ((const float4*)x)[i];
        v.x = to_tf32(v.x); v.y = to_tf32(v.y); v.z = to_tf32(v.z); v.w = to_tf32(v.w);
        ((float4*)xr)[i] = v;
    }
}

// ---------------- weight prep: transpose to [OUT][KD], cvt to tf32; fused biases ----------------
__global__ void prep_weights(const float* __restrict__ W0, const float* __restrict__ Ws0,
                             const float* __restrict__ W1, const float* __restrict__ Ws1,
                             const float* __restrict__ W2, const float* __restrict__ Ws2,
                             const float* __restrict__ Wm,
                             const float* __restrict__ b0, const float* __restrict__ bs0,
                             const float* __restrict__ b1, const float* __restrict__ bs1,
                             const float* __restrict__ b2, const float* __restrict__ bs2,
                             const float* __restrict__ bm,
                             float* __restrict__ Wt0, float* __restrict__ Wt1,
                             float* __restrict__ Wt2, float* __restrict__ Wtm,
                             float* __restrict__ bias0, float* __restrict__ bias1,
                             float* __restrict__ bias2, float* __restrict__ biasm) {
    int idx = blockIdx.x * blockDim.x + threadIdx.x;
    const int S0 = 448 * 128, S1 = 448 * 64, S2 = 448 * 64, SM = 64 * 192;
    if (idx < S0) {
        int n = idx / 128, k = idx % 128;
        float v = (n < 384) ? W0[(size_t)(n / 64) * 128 * 64 + (size_t)k * 64 + (n % 64)]
                            : Ws0[(size_t)k * 64 + (n - 384)];
        Wt0[idx] = to_tf32(v);
        return;
    }
    idx -= S0;
    if (idx < S1) {
        int n = idx / 64, k = idx % 64;
        float v = (n < 384) ? W1[(size_t)(n / 64) * 64 * 64 + (size_t)k * 64 + (n % 64)]
                            : Ws1[(size_t)k * 64 + (n - 384)];
        Wt1[idx] = to_tf32(v);
        return;
    }
    idx -= S1;
    if (idx < S2) {
        int n = idx / 64, k = idx % 64;
        float v = (n < 384) ? W2[(size_t)(n / 64) * 64 * 64 + (size_t)k * 64 + (n % 64)]
                            : Ws2[(size_t)k * 64 + (n - 384)];
        Wt2[idx] = to_tf32(v);
        return;
    }
    idx -= S2;
    if (idx < SM) {
        int n = idx / 192, k = idx % 192;
        float v = (n < 32) ? Wm[(size_t)k * 32 + n]
                           : Wm[(size_t)192 * 32 + (size_t)k * 32 + (n - 32)];
        Wtm[idx] = to_tf32(v);
        return;
    }
    idx -= SM;
    if (idx < 448) { bias0[idx] = (idx < 64) ? b0[idx] : (idx >= 384 ? bs0[idx - 384] : 0.f); return; }
    idx -= 448;
    if (idx < 448) { bias1[idx] = (idx < 64) ? b1[idx] : (idx >= 384 ? bs1[idx - 384] : 0.f); return; }
    idx -= 448;
    if (idx < 448) { bias2[idx] = (idx < 64) ? b2[idx] : (idx >= 384 ? bs2[idx - 384] : 0.f); return; }
    idx -= 448;
    if (idx < 64) { biasm[idx] = (idx < 32) ? bm[idx] : 0.f; return; }
}

// ---------------- mma.sync tf32 GEMM (cp.async 2-stage double buffer, R8-frozen) ----------------
template<int KD, int SPLIT, int WLO, int WHI>
__global__ __launch_bounds__(256)
void gemm_mma(const float* __restrict__ A, const float* __restrict__ A2,
              const float* __restrict__ Wt, const float* __restrict__ biasfull,
              const float* __restrict__ dis, __half* __restrict__ Hout,
              float* __restrict__ C, int OUT, int N) {
    constexpr int BM = 128, BN = 64, LDA = 36;
    constexpr int NKT = KD / 32;
    constexpr int A2S = (KD > SPLIT) ? (KD - SPLIT) : 1;
    __shared__ float As[2][BM * LDA];
    __shared__ float Bs[2][BN * LDA];

    int tid = threadIdx.x;
    int lane = tid & 31, wid = tid >> 5;
    int wm = wid & 3, wn = wid >> 2;
    int quad = lane >> 2, qt = lane & 3;
    int br = blockIdx.x * BM;
    int colbase = blockIdx.y * BN;

    float acc[2][4][4];
    #pragma unroll
    for (int mi = 0; mi < 2; mi++)
        #pragma unroll
        for (int ni = 0; ni < 4; ni++)
            #pragma unroll
            for (int j = 0; j < 4; j++) acc[mi][ni][j] = 0.f;

    int ar[4], ac4[4], bn_[2], bc4[2];
    #pragma unroll
    for (int t = 0; t < 4; t++) {
        int i4 = tid + 256 * t;
        ar[t] = i4 >> 3; ac4[t] = i4 & 7;
    }
    #pragma unroll
    for (int t = 0; t < 2; t++) {
        int i4 = tid + 256 * t;
        bn_[t] = i4 >> 3; bc4[t] = i4 & 7;
    }

    uint32_t sA[2], sB[2];
    sA[0] = (uint32_t)__cvta_generic_to_shared(As[0]);
    sA[1] = (uint32_t)__cvta_generic_to_shared(As[1]);
    sB[0] = (uint32_t)__cvta_generic_to_shared(Bs[0]);
    sB[1] = (uint32_t)__cvta_generic_to_shared(Bs[1]);

    auto issue = [&](int kt, int s) {
        int k0 = kt * 32;
        #pragma unroll
        for (int t = 0; t < 4; t++) {
            int gr = br + ar[t];
            int col = k0 + ac4[t] * 4;
            const float* src;
            if (SPLIT == KD || col < SPLIT) src = A + (size_t)gr * SPLIT + col;
            else                            src = A2 + (size_t)gr * A2S + (col - SPLIT);
            cp_async16(sA[s] + (ar[t] * LDA + ac4[t] * 4) * 4, src, gr < N);
        }
        #pragma unroll
        for (int t = 0; t < 2; t++)
            cp_async16(sB[s] + (bn_[t] * LDA + bc4[t] * 4) * 4,
                       Wt + (size_t)(colbase + bn_[t]) * KD + k0 + bc4[t] * 4, true);
        CP_COMMIT();
    };

    issue(0, 0);
    #pragma unroll
    for (int kt = 0; kt < NKT; kt++) {
        int s = kt & 1;
        if (kt + 1 < NKT) {
            issue(kt + 1, (kt + 1) & 1);
            asm volatile("cp.async.wait_group 1;\n" ::: "memory");
        } else {
            asm volatile("cp.async.wait_group 0;\n" ::: "memory");
        }
        __syncthreads();
        const uint32_t* Asu = (const uint32_t*)As[s];
        const uint32_t* Bsu = (const uint32_t*)Bs[s];
        #pragma unroll
        for (int ks = 0; ks < 4; ks++) {
            int kk = ks * 8;
            uint32_t a[2][4];
            #pragma unroll
            for (int mi = 0; mi < 2; mi++) {
                int row = wm * 32 + mi * 16 + quad;
                a[mi][0] = Asu[row * LDA + kk + qt];
                a[mi][1] = Asu[(row + 8) * LDA + kk + qt];
                a[mi][2] = Asu[row * LDA + kk + qt + 4];
                a[mi][3] = Asu[(row + 8) * LDA + kk + qt + 4];
            }
            #pragma unroll
            for (int ni = 0; ni < 4; ni++) {
                int col = wn * 32 + ni * 8 + quad;
                uint32_t b0 = Bsu[col * LDA + kk + qt];
                uint32_t b1 = Bsu[col * LDA + kk + qt + 4];
                #pragma unroll
                for (int mi = 0; mi < 2; mi++)
                    mma_m16n8k8(acc[mi][ni], a[mi][0], a[mi][1], a[mi][2], a[mi][3], b0, b1);
            }
        }
        __syncthreads();
    }
    #pragma unroll
    for (int mi = 0; mi < 2; mi++) {
        int r0 = br + wm * 32 + mi * 16 + quad;
        float d0 = 0.f, d1 = 0.f;
        if (WHI > WLO) {
            if (r0 < N) d0 = __ldg(dis + r0);
            if (r0 + 8 < N) d1 = __ldg(dis + r0 + 8);
        }
        #pragma unroll
        for (int ni = 0; ni < 4; ni++) {
            int cg = colbase + wn * 32 + ni * 8 + qt * 2;
            float bx = __ldg(biasfull + cg), by = __ldg(biasfull + cg + 1);
            float v0x = acc[mi][ni][0] + bx, v0y = acc[mi][ni][1] + by;
            float v1x = acc[mi][ni][2] + bx, v1y = acc[mi][ni][3] + by;
            bool inw = (WHI > WLO) && cg >= WLO && cg < WHI;
            if (r0 < N) {
                *(float2*)(C + (size_t)r0 * OUT + cg) = make_float2(v0x, v0y);
                if (inw)
                    ((__half2*)Hout)[(size_t)r0 * ((WHI - WLO) / 2) + (cg - WLO) / 2] =
                        __floats2half2_rn(d0 * v0x, d0 * v0y);
            }
            if (r0 + 8 < N) {
                *(float2*)(C + (size_t)(r0 + 8) * OUT + cg) = make_float2(v1x, v1y);
                if (inw)
                    ((__half2*)Hout)[(size_t)(r0 + 8) * ((WHI - WLO) / 2) + (cg - WLO) / 2] =
                        __floats2half2_rn(d1 * v1x, d1 * v1y);
            }
        }
    }
}

// ---------------- Clenshaw propagation (R8 loop body; fp16 sub/out variants) ----------------
// v = scale*dis[d]*sum(gather fp16) + add - (subf | subh); relu?; + skip
// outputs: out (fp32, opt, tf32-roundable) | outs (fp16 of v, opt) | outh (fp16 of dis*v, opt)
template<int F>
__global__ __launch_bounds__(256)
void clenshaw_prop(const int* __restrict__ rowptr, const int* __restrict__ esrc,
                   const __half* __restrict__ tin_h,
                   const float* __restrict__ add, int add_stride,
                   const float* __restrict__ subf, int subf_stride,
                   const __half* __restrict__ subh,
                   const float* __restrict__ skip, int skip_stride,
                   const float* __restrict__ dis,
                   float* __restrict__ out, int out_stride,
                   __half* __restrict__ outs, __half* __restrict__ outh,
                   float scale, int do_relu, int tf32_out, int n) {
    constexpr int L = F / 2;
    int gt = blockIdx.x * blockDim.x + threadIdx.x;
    int node = gt / L;
    if (node >= n) return;
    int sl = gt & (L - 1);
    int beg = __ldg(rowptr + node), end = __ldg(rowptr + node + 1);
    const __half2* tin2 = (const __half2*)tin_h;
    float2 a0 = make_float2(0.f, 0.f), a1 = make_float2(0.f, 0.f);
    float2 a2 = make_float2(0.f, 0.f), a3 = make_float2(0.f, 0.f);
    int p = beg;
    for (; p + 8 <= end; p += 8) {
        int s0 = __ldg(esrc + p),     s1 = __ldg(esrc + p + 1);
        int s2 = __ldg(esrc + p + 2), s3 = __ldg(esrc + p + 3);
        int s4 = __ldg(esrc + p + 4), s5 = __ldg(esrc + p + 5);
        int s6 = __ldg(esrc + p + 6), s7 = __ldg(esrc + p + 7);
        float2 f0 = __half22float2(__ldg(tin2 + (size_t)s0 * L + sl));
        float2 f1 = __half22float2(__ldg(tin2 + (size_t)s1 * L + sl));
        float2 f2 = __half22float2(__ldg(tin2 + (size_t)s2 * L + sl));
        float2 f3 = __half22float2(__ldg(tin2 + (size_t)s3 * L + sl));
        float2 f4 = __half22float2(__ldg(tin2 + (size_t)s4 * L + sl));
        float2 f5 = __half22float2(__ldg(tin2 + (size_t)s5 * L + sl));
        float2 f6 = __half22float2(__ldg(tin2 + (size_t)s6 * L + sl));
        float2 f7 = __half22float2(__ldg(tin2 + (size_t)s7 * L + sl));
        a0.x += f0.x + f4.x; a0.y += f0.y + f4.y;
        a1.x += f1.x + f5.x; a1.y += f1.y + f5.y;
        a2.x += f2.x + f6.x; a2.y += f2.y + f6.y;
        a3.x += f3.x + f7.x; a3.y += f3.y + f7.y;
    }
    for (; p < end; ++p) {
        int s = __ldg(esrc + p);
        float2 f = __half22float2(__ldg(tin2 + (size_t)s * L + sl));
        a0.x += f.x; a0.y += f.y;
    }
    float d = __ldg(dis + node);
    float sd = scale * d;
    float vx = sd * ((a0.x + a1.x) + (a2.x + a3.x));
    float vy = sd * ((a0.y + a1.y) + (a2.y + a3.y));
    float2 ad = ((const float2*)(add + (size_t)node * add_stride))[sl];
    vx += ad.x; vy += ad.y;
    if (subf) {
        float2 s = ((const float2*)(subf + (size_t)node * subf_stride))[sl];
        vx -= s.x; vy -= s.y;
    } else if (subh) {
        float2 s = __half22float2(((const __half2*)subh)[(size_t)node * L + sl]);
        vx -= s.x; vy -= s.y;
    }
    if (do_relu) { vx = fmaxf(vx, 0.f); vy = fmaxf(vy, 0.f); }
    if (skip) {
        float2 s = ((const float2*)(skip + (size_t)node * skip_stride))[sl];
        vx += s.x; vy += s.y;
    }
    if (out) {
        float wx = tf32_out ? to_tf32(vx) : vx;
        float wy = tf32_out ? to_tf32(vy) : vy;
        ((float2*)(out + (size_t)node * out_stride))[sl] = make_float2(wx, wy);
    }
    if (outs)
        ((__half2*)outs)[(size_t)node * L + sl] = __floats2half2_rn(vx, vy);
    if (outh)
        ((__half2*)outh)[(size_t)node * L + sl] = __floats2half2_rn(d * vx, d * vy);
}

// ---------------- host orchestration ----------------
static void prop64(const int* rowptr, const int* esrc, const __half* tin_h,
                   const float* add, int as,
                   const float* subf, int sfs, const __half* subh,
                   const float* skip, int ks, const float* dis,
                   float* out, int os, __half* outs, __half* outh,
                   float scale, int relu, int tf32o) {
    int blocks = (NN * 32 + 255) / 256;
    clenshaw_prop<64><<<blocks, 256>>>(rowptr, esrc, tin_h, add, as, subf, sfs, subh,
                                       skip, ks, dis, out, os, outs, outh,
                                       scale, relu, tf32o, NN);
}

static void cheb_layer(const float* h, int kd,
                       const float* Wt, const float* biasfull,
                       float* hout, const int* rowptr, const int* esrc,
                       const float* dis, float* C,
                       __half* H0, __half* H1, __half* H2, __half* H3,
                       __half* S0, __half* S1, __half* S2) {
    dim3 grid((NN + 127) / 128, 7);
    if (kd == 128)
        gemm_mma<128, 128, 320, 384><<<grid, 256>>>(h, nullptr, Wt, biasfull, dis, H3, C, 448, NN);
    else
        gemm_mma<64, 64, 320, 384><<<grid, 256>>>(h, nullptr, Wt, biasfull, dis, H3, C, 448, NN);
    // b4 = c4 + 2L b5                    -> S0 (fp16 value), H0 (gather)
    prop64(rowptr, esrc, H3, C + 4 * 64, 448, nullptr, 0, nullptr,
           nullptr, 0, dis, nullptr, 0, S0, H0, -2.f, 0, 0);
    // b3 = c3 + 2L b4 - c5 (b5=c5, fp32 from C) -> S1, H1
    prop64(rowptr, esrc, H0, C + 3 * 64, 448, C + 5 * 64, 448, nullptr,
           nullptr, 0, dis, nullptr, 0, S1, H1, -2.f, 0, 0);
    // b2 = c2 + 2L b3 - b4 (fp16 S0)     -> S2, H2
    prop64(rowptr, esrc, H1, C + 2 * 64, 448, nullptr, 0, S0,
           nullptr, 0, dis, nullptr, 0, S2, H2, -2.f, 0, 0);
    // b1 = c1 + 2L b2 - b3 (fp16 S1)     -> H0 only (fp32 value was dead)
    prop64(rowptr, esrc, H2, C + 1 * 64, 448, nullptr, 0, S1,
           nullptr, 0, dis, nullptr, 0, nullptr, H0, -2.f, 0, 0);
    // h = relu(c0 + L b1 - b2 (fp16 S2)) + skip -> hout fp32 (tf32-rounded for next GEMM)
    prop64(rowptr, esrc, H0, C, 448, nullptr, 0, S2,
           C + 6 * 64, 448, dis, hout, 64, nullptr, nullptr, -1.f, 1, 1);
}

extern "C" void kernel_launch(void* const* d_in, const int* in_sizes, int n_in,
                              void* d_out, int out_size) {
    const float* x   = (const float*)d_in[0];
    const int*   ei  = (const int*)d_in[1];
    const float* W0  = (const float*)d_in[2];
    const float* b0  = (const float*)d_in[3];
    const float* Ws0 = (const float*)d_in[4];
    const float* bs0 = (const float*)d_in[5];
    const float* W1  = (const float*)d_in[6];
    const float* b1  = (const float*)d_in[7];
    const float* Ws1 = (const float*)d_in[8];
    const float* bs1 = (const float*)d_in[9];
    const float* W2  = (const float*)d_in[10];
    const float* b2  = (const float*)d_in[11];
    const float* Ws2 = (const float*)d_in[12];
    const float* bs2 = (const float*)d_in[13];
    const float* Wm  = (const float*)d_in[14];
    const float* bm  = (const float*)d_in[15];
    float* out = (float*)d_out;

    const int* src = ei;
    const int* dst = ei + NE;

    void* p;
    cudaGetSymbolAddress(&p, g_cnt);     int*    cnt     = (int*)p;
    cudaGetSymbolAddress(&p, g_partial); int*    partial = (int*)p;
    cudaGetSymbolAddress(&p, g_rowptr);  int*    rowptr  = (int*)p;
    cudaGetSymbolAddress(&p, g_cursor);  int*    cursor  = (int*)p;
    cudaGetSymbolAddress(&p, g_dis);     float*  dis     = (float*)p;
    cudaGetSymbolAddress(&p, g_esrc);    int*    esrc    = (int*)p;
    cudaGetSymbolAddress(&p, g_xr);      float*  xr      = (float*)p;
    cudaGetSymbolAddress(&p, g_C);       float*  C       = (float*)p;
    cudaGetSymbolAddress(&p, g_H0);      __half* H0      = (__half*)p;
    cudaGetSymbolAddress(&p, g_H1);      __half* H1      = (__half*)p;
    cudaGetSymbolAddress(&p, g_H2);      __half* H2      = (__half*)p;
    cudaGetSymbolAddress(&p, g_H3);      __half* H3      = (__half*)p;
    cudaGetSymbolAddress(&p, g_S0);      __half* S0      = (__half*)p;
    cudaGetSymbolAddress(&p, g_S1);      __half* S1      = (__half*)p;
    cudaGetSymbolAddress(&p, g_S2);      __half* S2      = (__half*)p;
    cudaGetSymbolAddress(&p, g_h1);      float*  h1      = (float*)p;
    cudaGetSymbolAddress(&p, g_h2);      float*  h2      = (float*)p;
    cudaGetSymbolAddress(&p, g_Wt0);     float*  Wt0     = (float*)p;
    cudaGetSymbolAddress(&p, g_Wt1);     float*  Wt1     = (float*)p;
    cudaGetSymbolAddress(&p, g_Wt2);     float*  Wt2     = (float*)p;
    cudaGetSymbolAddress(&p, g_Wtm);     float*  Wtm     = (float*)p;
    cudaGetSymbolAddress(&p, g_bias0);   float*  bias0   = (float*)p;
    cudaGetSymbolAddress(&p, g_bias1);   float*  bias1   = (float*)p;
    cudaGetSymbolAddress(&p, g_bias2);   float*  bias2   = (float*)p;
    cudaGetSymbolAddress(&p, g_biasm);   float*  biasm   = (float*)p;

    // ---- weight prep + x rounding ----
    {
        int total = 448 * 128 + 448 * 64 + 448 * 64 + 64 * 192 + 448 * 3 + 64;
        prep_weights<<<(total + 255) / 256, 256>>>(W0, Ws0, W1, Ws1, W2, Ws2, Wm,
                                                   b0, bs0, b1, bs1, b2, bs2, bm,
                                                   Wt0, Wt1, Wt2, Wtm,
                                                   bias0, bias1, bias2, biasm);
        round_x<<<(NN * 32 + 255) / 256, 256>>>(x, xr, NN * 32);
    }

    // ---- preprocessing: degree + dis, CSR (sorted by dst) ----
    cudaMemsetAsync(cnt, 0, NN * sizeof(int), 0);
    hist_kernel<<<(NE + 255) / 256, 256>>>(dst, cnt, NE);
    int nb = (NN + 255) / 256;
    reduce_kernel<<<nb, 256>>>(cnt, partial, NN);
    scanp_kernel<<<1, 512>>>(partial, nb, rowptr + NN);
    apply_kernel<<<nb, 256>>>(cnt, partial, rowptr, cursor, dis, NN);
    fill_kernel<<<(NE + 255) / 256, 256>>>(src, dst, cursor, esrc, NE);

    // ---- 3 Kipf blocks (Clenshaw, fp16 gather + fp16 sub buffers) ----
    cheb_layer(xr,  128, Wt0, bias0, h1, rowptr, esrc, dis, C, H0, H1, H2, H3, S0, S1, S2);
    cheb_layer(h1,   64, Wt1, bias1, h2, rowptr, esrc, dis, C, H0, H1, H2, H3, S0, S1, S2);
    cheb_layer(h2,   64, Wt2, bias2, h1, rowptr, esrc, dis, C, H0, H1, H2, H3, S0, S1, S2);

    // ---- mix head: dual-source GEMM (h1 | xr) -> ChebConv K=2 -> out ----
    {
        dim3 grid((NN + 127) / 128, 1);
        // Cmix[N,64] -> reuse C as scratch (stride 64); fused H0 = dis ⊙ c1 (cols [32,64))
        gemm_mma<192, 64, 32, 64><<<grid, 256>>>(h1, xr, Wtm, biasm, dis, H0, C, 64, NN);
        int blocks = (NN * 16 + 255) / 256;
        clenshaw_prop<32><<<blocks, 256>>>(rowptr, esrc, H0, C, 64, nullptr, 0, nullptr,
                                           nullptr, 0, dis, out, 32, nullptr, nullptr,
                                           -1.f, 0, 0, NN);
    }
}

// round 15
// speedup vs baseline: 1.0453x; 1.0267x over previous
#include <cuda_runtime.h>
#include <cuda_fp16.h>
#include <cstdint>

#define NN 100000
#define NE 3200000
#define NH 64

// ---------------- scratch (__device__ globals: allocation-free) ----------------
__device__ int    g_cnt[NN];
__device__ int    g_partial[512];
__device__ int    g_rowptr[NN + 1];
__device__ int    g_cursor[NN];
__device__ float  g_dis[NN];
__device__ int    g_esrc[NE];             // CSR-by-dst src indices (weights separable)
__device__ float  g_xr[(size_t)NN * 128]; // tf32-rounded copy of x (GEMM A operand)
__device__ float  g_C[(size_t)NN * 64];   // fp32 mix-head GEMM output
__device__ __half g_Ch[(size_t)NN * 448]; // fp16 fused layer-GEMM output: c_0..c_5 | skip
__device__ __half g_H0[NN * NH];          // pre-scaled (dis⊙) fp16 gather buffers
__device__ __half g_H1[NN * NH];
__device__ __half g_H2[NN * NH];
__device__ __half g_H3[NN * NH];
__device__ __half g_S0[NN * NH];          // fp16 Clenshaw b_k value buffers (sub operands)
__device__ __half g_S1[NN * NH];
__device__ __half g_S2[NN * NH];
__device__ float  g_h1[NN * NH];
__device__ float  g_h2[NN * NH];
// tf32 transposed weights (rows = output col, contiguous K) + fused bias vectors
__device__ float g_Wt0[448 * 128];
__device__ float g_Wt1[448 * 64];
__device__ float g_Wt2[448 * 64];
__device__ float g_Wtm[64 * 192];
__device__ float g_bias0[448];
__device__ float g_bias1[448];
__device__ float g_bias2[448];
__device__ float g_biasm[64];

__device__ __forceinline__ float to_tf32(float v) {
    uint32_t u;
    asm("cvt.rna.tf32.f32 %0, %1;" : "=r"(u) : "f"(v));
    return __uint_as_float(u);
}

__device__ __forceinline__ void mma_m16n8k8(float* c, uint32_t a0, uint32_t a1,
                                            uint32_t a2, uint32_t a3,
                                            uint32_t b0, uint32_t b1) {
    asm volatile(
        "mma.sync.aligned.m16n8k8.row.col.f32.tf32.tf32.f32 "
        "{%0,%1,%2,%3}, {%4,%5,%6,%7}, {%8,%9}, {%0,%1,%2,%3};"
        : "+f"(c[0]), "+f"(c[1]), "+f"(c[2]), "+f"(c[3])
        : "r"(a0), "r"(a1), "r"(a2), "r"(a3), "r"(b0), "r"(b1));
}

__device__ __forceinline__ void cp_async16(uint32_t saddr, const void* gptr, bool pred) {
    int sz = pred ? 16 : 0;
    asm volatile("cp.async.cg.shared.global [%0], [%1], 16, %2;\n"
                 :: "r"(saddr), "l"(gptr), "r"(sz));
}
#define CP_COMMIT() asm volatile("cp.async.commit_group;\n" ::: "memory")

// ---------------- graph preprocessing ----------------
__global__ void hist_kernel(const int* __restrict__ dst, int* __restrict__ cnt, int E) {
    int i = blockIdx.x * blockDim.x + threadIdx.x;
    if (i < E) atomicAdd(&cnt[dst[i]], 1);
}

__global__ void reduce_kernel(const int* __restrict__ cnt, int* __restrict__ partial, int n) {
    __shared__ int s[8];
    int i = blockIdx.x * 256 + threadIdx.x;
    int v = (i < n) ? cnt[i] : 0;
    #pragma unroll
    for (int o = 16; o; o >>= 1) v += __shfl_down_sync(0xffffffffu, v, o);
    if ((threadIdx.x & 31) == 0) s[threadIdx.x >> 5] = v;
    __syncthreads();
    if (threadIdx.x < 8) {
        int t = s[threadIdx.x];
        #pragma unroll
        for (int o = 4; o; o >>= 1) t += __shfl_down_sync(0xffu, t, o);
        if (threadIdx.x == 0) partial[blockIdx.x] = t;
    }
}

__global__ void scanp_kernel(int* __restrict__ partial, int nb, int* __restrict__ total_out) {
    __shared__ int ws[16];
    int tid = threadIdx.x, lane = tid & 31, w = tid >> 5;
    int v = (tid < nb) ? partial[tid] : 0;
    int x = v;
    #pragma unroll
    for (int o = 1; o < 32; o <<= 1) {
        int y = __shfl_up_sync(0xffffffffu, x, o);
        if (lane >= o) x += y;
    }
    if (lane == 31) ws[w] = x;
    __syncthreads();
    if (w == 0 && lane < 16) {
        int t = ws[lane];
        #pragma unroll
        for (int o = 1; o < 16; o <<= 1) {
            int y = __shfl_up_sync(0xffffu, t, o);
            if (lane >= o) t += y;
        }
        ws[lane] = t;
    }
    __syncthreads();
    int excl = x - v + (w ? ws[w - 1] : 0);
    if (tid < nb) partial[tid] = excl;
    if (tid == nb - 1) total_out[0] = excl + v;
}

// block-scan apply + fused dis = rsqrt(deg)
__global__ void apply_kernel(const int* __restrict__ cnt, const int* __restrict__ partial,
                             int* __restrict__ rowptr, int* __restrict__ cursor,
                             float* __restrict__ dis, int n) {
    __shared__ int ws[8];
    int i = blockIdx.x * 256 + threadIdx.x;
    int lane = threadIdx.x & 31, w = threadIdx.x >> 5;
    int v = (i < n) ? cnt[i] : 0;
    int x = v;
    #pragma unroll
    for (int o = 1; o < 32; o <<= 1) {
        int y = __shfl_up_sync(0xffffffffu, x, o);
        if (lane >= o) x += y;
    }
    if (lane == 31) ws[w] = x;
    __syncthreads();
    if (w == 0 && lane < 8) {
        int t = ws[lane];
        #pragma unroll
        for (int o = 1; o < 8; o <<= 1) {
            int y = __shfl_up_sync(0xffu, t, o);
            if (lane >= o) t += y;
        }
        ws[lane] = t;
    }
    __syncthreads();
    int excl = x - v + (w ? ws[w - 1] : 0) + partial[blockIdx.x];
    if (i < n) {
        rowptr[i] = excl;
        cursor[i] = excl;
        dis[i] = v > 0 ? rsqrtf((float)v) : 0.0f;
    }
}

__global__ void fill_kernel(const int* __restrict__ src, const int* __restrict__ dst,
                            int* __restrict__ cursor, int* __restrict__ esrc, int E) {
    int i = blockIdx.x * blockDim.x + threadIdx.x;
    if (i < E) {
        int d = dst[i];
        int pos = atomicAdd(&cursor[d], 1);
        esrc[pos] = src[i];
    }
}

// round x to tf32 once (preserves cvt.rna semantics for cp.async GEMM path)
__global__ void round_x(const float* __restrict__ x, float* __restrict__ xr, int total4) {
    int i = blockIdx.x * blockDim.x + threadIdx.x;
    if (i < total4) {
        float4 v = ((const float4*)x)[i];
        v.x = to_tf32(v.x); v.y = to_tf32(v.y); v.z = to_tf32(v.z); v.w = to_tf32(v.w);
        ((float4*)xr)[i] = v;
    }
}

// ---------------- weight prep: transpose to [OUT][KD], cvt to tf32; fused biases ----------------
__global__ void prep_weights(const float* __restrict__ W0, const float* __restrict__ Ws0,
                             const float* __restrict__ W1, const float* __restrict__ Ws1,
                             const float* __restrict__ W2, const float* __restrict__ Ws2,
                             const float* __restrict__ Wm,
                             const float* __restrict__ b0, const float* __restrict__ bs0,
                             const float* __restrict__ b1, const float* __restrict__ bs1,
                             const float* __restrict__ b2, const float* __restrict__ bs2,
                             const float* __restrict__ bm,
                             float* __restrict__ Wt0, float* __restrict__ Wt1,
                             float* __restrict__ Wt2, float* __restrict__ Wtm,
                             float* __restrict__ bias0, float* __restrict__ bias1,
                             float* __restrict__ bias2, float* __restrict__ biasm) {
    int idx = blockIdx.x * blockDim.x + threadIdx.x;
    const int S0 = 448 * 128, S1 = 448 * 64, S2 = 448 * 64, SM = 64 * 192;
    if (idx < S0) {
        int n = idx / 128, k = idx % 128;
        float v = (n < 384) ? W0[(size_t)(n / 64) * 128 * 64 + (size_t)k * 64 + (n % 64)]
                            : Ws0[(size_t)k * 64 + (n - 384)];
        Wt0[idx] = to_tf32(v);
        return;
    }
    idx -= S0;
    if (idx < S1) {
        int n = idx / 64, k = idx % 64;
        float v = (n < 384) ? W1[(size_t)(n / 64) * 64 * 64 + (size_t)k * 64 + (n % 64)]
                            : Ws1[(size_t)k * 64 + (n - 384)];
        Wt1[idx] = to_tf32(v);
        return;
    }
    idx -= S1;
    if (idx < S2) {
        int n = idx / 64, k = idx % 64;
        float v = (n < 384) ? W2[(size_t)(n / 64) * 64 * 64 + (size_t)k * 64 + (n % 64)]
                            : Ws2[(size_t)k * 64 + (n - 384)];
        Wt2[idx] = to_tf32(v);
        return;
    }
    idx -= S2;
    if (idx < SM) {
        int n = idx / 192, k = idx % 192;
        float v = (n < 32) ? Wm[(size_t)k * 32 + n]
                           : Wm[(size_t)192 * 32 + (size_t)k * 32 + (n - 32)];
        Wtm[idx] = to_tf32(v);
        return;
    }
    idx -= SM;
    if (idx < 448) { bias0[idx] = (idx < 64) ? b0[idx] : (idx >= 384 ? bs0[idx - 384] : 0.f); return; }
    idx -= 448;
    if (idx < 448) { bias1[idx] = (idx < 64) ? b1[idx] : (idx >= 384 ? bs1[idx - 384] : 0.f); return; }
    idx -= 448;
    if (idx < 448) { bias2[idx] = (idx < 64) ? b2[idx] : (idx >= 384 ? bs2[idx - 384] : 0.f); return; }
    idx -= 448;
    if (idx < 64) { biasm[idx] = (idx < 32) ? bm[idx] : 0.f; return; }
}

// ---------------- mma.sync tf32 GEMM (cp.async 2-stage double buffer) ----------------
// If Chh != nullptr: outputs stored fp16 to Chh (stride OUT); else fp32 to C.
// Hout (optional): dis-scaled fp16 copy of cols [WLO,WHI).
template<int KD, int SPLIT, int WLO, int WHI>
__global__ __launch_bounds__(256)
void gemm_mma(const float* __restrict__ A, const float* __restrict__ A2,
              const float* __restrict__ Wt, const float* __restrict__ biasfull,
              const float* __restrict__ dis, __half* __restrict__ Hout,
              float* __restrict__ C, __half* __restrict__ Chh, int OUT, int N) {
    constexpr int BM = 128, BN = 64, LDA = 36;
    constexpr int NKT = KD / 32;
    constexpr int A2S = (KD > SPLIT) ? (KD - SPLIT) : 1;
    __shared__ float As[2][BM * LDA];
    __shared__ float Bs[2][BN * LDA];

    int tid = threadIdx.x;
    int lane = tid & 31, wid = tid >> 5;
    int wm = wid & 3, wn = wid >> 2;
    int quad = lane >> 2, qt = lane & 3;
    int br = blockIdx.x * BM;
    int colbase = blockIdx.y * BN;

    float acc[2][4][4];
    #pragma unroll
    for (int mi = 0; mi < 2; mi++)
        #pragma unroll
        for (int ni = 0; ni < 4; ni++)
            #pragma unroll
            for (int j = 0; j < 4; j++) acc[mi][ni][j] = 0.f;

    int ar[4], ac4[4], bn_[2], bc4[2];
    #pragma unroll
    for (int t = 0; t < 4; t++) {
        int i4 = tid + 256 * t;
        ar[t] = i4 >> 3; ac4[t] = i4 & 7;
    }
    #pragma unroll
    for (int t = 0; t < 2; t++) {
        int i4 = tid + 256 * t;
        bn_[t] = i4 >> 3; bc4[t] = i4 & 7;
    }

    uint32_t sA[2], sB[2];
    sA[0] = (uint32_t)__cvta_generic_to_shared(As[0]);
    sA[1] = (uint32_t)__cvta_generic_to_shared(As[1]);
    sB[0] = (uint32_t)__cvta_generic_to_shared(Bs[0]);
    sB[1] = (uint32_t)__cvta_generic_to_shared(Bs[1]);

    auto issue = [&](int kt, int s) {
        int k0 = kt * 32;
        #pragma unroll
        for (int t = 0; t < 4; t++) {
            int gr = br + ar[t];
            int col = k0 + ac4[t] * 4;
            const float* src;
            if (SPLIT == KD || col < SPLIT) src = A + (size_t)gr * SPLIT + col;
            else                            src = A2 + (size_t)gr * A2S + (col - SPLIT);
            cp_async16(sA[s] + (ar[t] * LDA + ac4[t] * 4) * 4, src, gr < N);
        }
        #pragma unroll
        for (int t = 0; t < 2; t++)
            cp_async16(sB[s] + (bn_[t] * LDA + bc4[t] * 4) * 4,
                       Wt + (size_t)(colbase + bn_[t]) * KD + k0 + bc4[t] * 4, true);
        CP_COMMIT();
    };

    issue(0, 0);
    #pragma unroll
    for (int kt = 0; kt < NKT; kt++) {
        int s = kt & 1;
        if (kt + 1 < NKT) {
            issue(kt + 1, (kt + 1) & 1);
            asm volatile("cp.async.wait_group 1;\n" ::: "memory");
        } else {
            asm volatile("cp.async.wait_group 0;\n" ::: "memory");
        }
        __syncthreads();
        const uint32_t* Asu = (const uint32_t*)As[s];
        const uint32_t* Bsu = (const uint32_t*)Bs[s];
        #pragma unroll
        for (int ks = 0; ks < 4; ks++) {
            int kk = ks * 8;
            uint32_t a[2][4];
            #pragma unroll
            for (int mi = 0; mi < 2; mi++) {
                int row = wm * 32 + mi * 16 + quad;
                a[mi][0] = Asu[row * LDA + kk + qt];
                a[mi][1] = Asu[(row + 8) * LDA + kk + qt];
                a[mi][2] = Asu[row * LDA + kk + qt + 4];
                a[mi][3] = Asu[(row + 8) * LDA + kk + qt + 4];
            }
            #pragma unroll
            for (int ni = 0; ni < 4; ni++) {
                int col = wn * 32 + ni * 8 + quad;
                uint32_t b0 = Bsu[col * LDA + kk + qt];
                uint32_t b1 = Bsu[col * LDA + kk + qt + 4];
                #pragma unroll
                for (int mi = 0; mi < 2; mi++)
                    mma_m16n8k8(acc[mi][ni], a[mi][0], a[mi][1], a[mi][2], a[mi][3], b0, b1);
            }
        }
        __syncthreads();
    }
    #pragma unroll
    for (int mi = 0; mi < 2; mi++) {
        int r0 = br + wm * 32 + mi * 16 + quad;
        float d0 = 0.f, d1 = 0.f;
        if (WHI > WLO) {
            if (r0 < N) d0 = __ldg(dis + r0);
            if (r0 + 8 < N) d1 = __ldg(dis + r0 + 8);
        }
        #pragma unroll
        for (int ni = 0; ni < 4; ni++) {
            int cg = colbase + wn * 32 + ni * 8 + qt * 2;
            float bx = __ldg(biasfull + cg), by = __ldg(biasfull + cg + 1);
            float v0x = acc[mi][ni][0] + bx, v0y = acc[mi][ni][1] + by;
            float v1x = acc[mi][ni][2] + bx, v1y = acc[mi][ni][3] + by;
            bool inw = (WHI > WLO) && cg >= WLO && cg < WHI;
            if (r0 < N) {
                if (Chh)
                    *(__half2*)(Chh + (size_t)r0 * OUT + cg) = __floats2half2_rn(v0x, v0y);
                else
                    *(float2*)(C + (size_t)r0 * OUT + cg) = make_float2(v0x, v0y);
                if (inw)
                    ((__half2*)Hout)[(size_t)r0 * ((WHI - WLO) / 2) + (cg - WLO) / 2] =
                        __floats2half2_rn(d0 * v0x, d0 * v0y);
            }
            if (r0 + 8 < N) {
                if (Chh)
                    *(__half2*)(Chh + (size_t)(r0 + 8) * OUT + cg) = __floats2half2_rn(v1x, v1y);
                else
                    *(float2*)(C + (size_t)(r0 + 8) * OUT + cg) = make_float2(v1x, v1y);
                if (inw)
                    ((__half2*)Hout)[(size_t)(r0 + 8) * ((WHI - WLO) / 2) + (cg - WLO) / 2] =
                        __floats2half2_rn(d1 * v1x, d1 * v1y);
            }
        }
    }
}

// ---------------- Clenshaw propagation (R8 loop body; fp16/fp32 operand variants) ----------------
// v = scale*dis[d]*sum(gather fp16) + (addh|addf) - (subh); relu?; + skiph
// outputs: out fp32 (opt, tf32-roundable) | outs fp16 of v (opt) | outh fp16 of dis*v (opt)
template<int F>
__global__ __launch_bounds__(256)
void clenshaw_prop(const int* __restrict__ rowptr, const int* __restrict__ esrc,
                   const __half* __restrict__ tin_h,
                   const __half* __restrict__ addh, int ah_s,
                   const float* __restrict__ addf, int af_s,
                   const __half* __restrict__ subh, int sh_s,
                   const __half* __restrict__ skiph, int kh_s,
                   const float* __restrict__ dis,
                   float* __restrict__ out, int out_stride,
                   __half* __restrict__ outs, __half* __restrict__ outh,
                   float scale, int do_relu, int tf32_out, int n) {
    constexpr int L = F / 2;
    int gt = blockIdx.x * blockDim.x + threadIdx.x;
    int node = gt / L;
    if (node >= n) return;
    int sl = gt & (L - 1);
    int beg = __ldg(rowptr + node), end = __ldg(rowptr + node + 1);
    const __half2* tin2 = (const __half2*)tin_h;
    float2 a0 = make_float2(0.f, 0.f), a1 = make_float2(0.f, 0.f);
    float2 a2 = make_float2(0.f, 0.f), a3 = make_float2(0.f, 0.f);
    int p = beg;
    for (; p + 8 <= end; p += 8) {
        int s0 = __ldg(esrc + p),     s1 = __ldg(esrc + p + 1);
        int s2 = __ldg(esrc + p + 2), s3 = __ldg(esrc + p + 3);
        int s4 = __ldg(esrc + p + 4), s5 = __ldg(esrc + p + 5);
        int s6 = __ldg(esrc + p + 6), s7 = __ldg(esrc + p + 7);
        float2 f0 = __half22float2(__ldg(tin2 + (size_t)s0 * L + sl));
        float2 f1 = __half22float2(__ldg(tin2 + (size_t)s1 * L + sl));
        float2 f2 = __half22float2(__ldg(tin2 + (size_t)s2 * L + sl));
        float2 f3 = __half22float2(__ldg(tin2 + (size_t)s3 * L + sl));
        float2 f4 = __half22float2(__ldg(tin2 + (size_t)s4 * L + sl));
        float2 f5 = __half22float2(__ldg(tin2 + (size_t)s5 * L + sl));
        float2 f6 = __half22float2(__ldg(tin2 + (size_t)s6 * L + sl));
        float2 f7 = __half22float2(__ldg(tin2 + (size_t)s7 * L + sl));
        a0.x += f0.x + f4.x; a0.y += f0.y + f4.y;
        a1.x += f1.x + f5.x; a1.y += f1.y + f5.y;
        a2.x += f2.x + f6.x; a2.y += f2.y + f6.y;
        a3.x += f3.x + f7.x; a3.y += f3.y + f7.y;
    }
    for (; p < end; ++p) {
        int s = __ldg(esrc + p);
        float2 f = __half22float2(__ldg(tin2 + (size_t)s * L + sl));
        a0.x += f.x; a0.y += f.y;
    }
    float d = __ldg(dis + node);
    float sd = scale * d;
    float vx = sd * ((a0.x + a1.x) + (a2.x + a3.x));
    float vy = sd * ((a0.y + a1.y) + (a2.y + a3.y));
    if (addh) {
        float2 ad = __half22float2(*(const __half2*)(addh + (size_t)node * ah_s + 2 * sl));
        vx += ad.x; vy += ad.y;
    } else {
        float2 ad = ((const float2*)(addf + (size_t)node * af_s))[sl];
        vx += ad.x; vy += ad.y;
    }
    if (subh) {
        float2 s = __half22float2(*(const __half2*)(subh + (size_t)node * sh_s + 2 * sl));
        vx -= s.x; vy -= s.y;
    }
    if (do_relu) { vx = fmaxf(vx, 0.f); vy = fmaxf(vy, 0.f); }
    if (skiph) {
        float2 s = __half22float2(*(const __half2*)(skiph + (size_t)node * kh_s + 2 * sl));
        vx += s.x; vy += s.y;
    }
    if (out) {
        float wx = tf32_out ? to_tf32(vx) : vx;
        float wy = tf32_out ? to_tf32(vy) : vy;
        ((float2*)(out + (size_t)node * out_stride))[sl] = make_float2(wx, wy);
    }
    if (outs)
        ((__half2*)outs)[(size_t)node * L + sl] = __floats2half2_rn(vx, vy);
    if (outh)
        ((__half2*)outh)[(size_t)node * L + sl] = __floats2half2_rn(d * vx, d * vy);
}

// ---------------- host orchestration ----------------
static void prop64(const int* rowptr, const int* esrc, const __half* tin_h,
                   const __half* addh, int ah_s,
                   const __half* subh, int sh_s,
                   const __half* skiph, int kh_s,
                   const float* dis,
                   float* out, int os, __half* outs, __half* outh,
                   float scale, int relu, int tf32o) {
    int blocks = (NN * 32 + 255) / 256;
    clenshaw_prop<64><<<blocks, 256>>>(rowptr, esrc, tin_h, addh, ah_s, nullptr, 0,
                                       subh, sh_s, skiph, kh_s, dis,
                                       out, os, outs, outh, scale, relu, tf32o, NN);
}

static void cheb_layer(const float* h, int kd,
                       const float* Wt, const float* biasfull,
                       float* hout, const int* rowptr, const int* esrc,
                       const float* dis, __half* Ch,
                       __half* H0, __half* H1, __half* H2, __half* H3,
                       __half* S0, __half* S1, __half* S2) {
    dim3 grid((NN + 127) / 128, 7);
    if (kd == 128)
        gemm_mma<128, 128, 320, 384><<<grid, 256>>>(h, nullptr, Wt, biasfull, dis, H3,
                                                    nullptr, Ch, 448, NN);
    else
        gemm_mma<64, 64, 320, 384><<<grid, 256>>>(h, nullptr, Wt, biasfull, dis, H3,
                                                  nullptr, Ch, 448, NN);
    // b4 = c4 + 2L b5                       -> S0 (fp16 value), H0 (gather)
    prop64(rowptr, esrc, H3, Ch + 4 * 64, 448, nullptr, 0, nullptr, 0,
           dis, nullptr, 0, S0, H0, -2.f, 0, 0);
    // b3 = c3 + 2L b4 - c5 (fp16 from Ch)   -> S1, H1
    prop64(rowptr, esrc, H0, Ch + 3 * 64, 448, Ch + 5 * 64, 448, nullptr, 0,
           dis, nullptr, 0, S1, H1, -2.f, 0, 0);
    // b2 = c2 + 2L b3 - b4 (S0)             -> S2, H2
    prop64(rowptr, esrc, H1, Ch + 2 * 64, 448, S0, 64, nullptr, 0,
           dis, nullptr, 0, S2, H2, -2.f, 0, 0);
    // b1 = c1 + 2L b2 - b3 (S1)             -> H0 only
    prop64(rowptr, esrc, H2, Ch + 1 * 64, 448, S1, 64, nullptr, 0,
           dis, nullptr, 0, nullptr, H0, -2.f, 0, 0);
    // h = relu(c0 + L b1 - b2 (S2)) + skip (fp16 Ch+384) -> hout fp32 (tf32-rounded)
    prop64(rowptr, esrc, H0, Ch, 448, S2, 64, Ch + 6 * 64, 448,
           dis, hout, 64, nullptr, nullptr, -1.f, 1, 1);
}

extern "C" void kernel_launch(void* const* d_in, const int* in_sizes, int n_in,
                              void* d_out, int out_size) {
    const float* x   = (const float*)d_in[0];
    const int*   ei  = (const int*)d_in[1];
    const float* W0  = (const float*)d_in[2];
    const float* b0  = (const float*)d_in[3];
    const float* Ws0 = (const float*)d_in[4];
    const float* bs0 = (const float*)d_in[5];
    const float* W1  = (const float*)d_in[6];
    const float* b1  = (const float*)d_in[7];
    const float* Ws1 = (const float*)d_in[8];
    const float* bs1 = (const float*)d_in[9];
    const float* W2  = (const float*)d_in[10];
    const float* b2  = (const float*)d_in[11];
    const float* Ws2 = (const float*)d_in[12];
    const float* bs2 = (const float*)d_in[13];
    const float* Wm  = (const float*)d_in[14];
    const float* bm  = (const float*)d_in[15];
    float* out = (float*)d_out;

    const int* src = ei;
    const int* dst = ei + NE;

    void* p;
    cudaGetSymbolAddress(&p, g_cnt);     int*    cnt     = (int*)p;
    cudaGetSymbolAddress(&p, g_partial); int*    partial = (int*)p;
    cudaGetSymbolAddress(&p, g_rowptr);  int*    rowptr  = (int*)p;
    cudaGetSymbolAddress(&p, g_cursor);  int*    cursor  = (int*)p;
    cudaGetSymbolAddress(&p, g_dis);     float*  dis     = (float*)p;
    cudaGetSymbolAddress(&p, g_esrc);    int*    esrc    = (int*)p;
    cudaGetSymbolAddress(&p, g_xr);      float*  xr      = (float*)p;
    cudaGetSymbolAddress(&p, g_C);       float*  C       = (float*)p;
    cudaGetSymbolAddress(&p, g_Ch);      __half* Ch      = (__half*)p;
    cudaGetSymbolAddress(&p, g_H0);      __half* H0      = (__half*)p;
    cudaGetSymbolAddress(&p, g_H1);      __half* H1      = (__half*)p;
    cudaGetSymbolAddress(&p, g_H2);      __half* H2      = (__half*)p;
    cudaGetSymbolAddress(&p, g_H3);      __half* H3      = (__half*)p;
    cudaGetSymbolAddress(&p, g_S0);      __half* S0      = (__half*)p;
    cudaGetSymbolAddress(&p, g_S1);      __half* S1      = (__half*)p;
    cudaGetSymbolAddress(&p, g_S2);      __half* S2      = (__half*)p;
    cudaGetSymbolAddress(&p, g_h1);      float*  h1      = (float*)p;
    cudaGetSymbolAddress(&p, g_h2);      float*  h2      = (float*)p;
    cudaGetSymbolAddress(&p, g_Wt0);     float*  Wt0     = (float*)p;
    cudaGetSymbolAddress(&p, g_Wt1);     float*  Wt1     = (float*)p;
    cudaGetSymbolAddress(&p, g_Wt2);     float*  Wt2     = (float*)p;
    cudaGetSymbolAddress(&p, g_Wtm);     float*  Wtm     = (float*)p;
    cudaGetSymbolAddress(&p, g_bias0);   float*  bias0   = (float*)p;
    cudaGetSymbolAddress(&p, g_bias1);   float*  bias1   = (float*)p;
    cudaGetSymbolAddress(&p, g_bias2);   float*  bias2   = (float*)p;
    cudaGetSymbolAddress(&p, g_biasm);   float*  biasm   = (float*)p;

    // ---- weight prep + x rounding ----
    {
        int total = 448 * 128 + 448 * 64 + 448 * 64 + 64 * 192 + 448 * 3 + 64;
        prep_weights<<<(total + 255) / 256, 256>>>(W0, Ws0, W1, Ws1, W2, Ws2, Wm,
                                                   b0, bs0, b1, bs1, b2, bs2, bm,
                                                   Wt0, Wt1, Wt2, Wtm,
                                                   bias0, bias1, bias2, biasm);
        round_x<<<(NN * 32 + 255) / 256, 256>>>(x, xr, NN * 32);
    }

    // ---- preprocessing: degree + dis, CSR (sorted by dst) ----
    cudaMemsetAsync(cnt, 0, NN * sizeof(int), 0);
    hist_kernel<<<(NE + 255) / 256, 256>>>(dst, cnt, NE);
    int nb = (NN + 255) / 256;
    reduce_kernel<<<nb, 256>>>(cnt, partial, NN);
    scanp_kernel<<<1, 512>>>(partial, nb, rowptr + NN);
    apply_kernel<<<nb, 256>>>(cnt, partial, rowptr, cursor, dis, NN);
    fill_kernel<<<(NE + 255) / 256, 256>>>(src, dst, cursor, esrc, NE);

    // ---- 3 Kipf blocks (Clenshaw, fp16 GEMM output + fp16 gather/sub buffers) ----
    cheb_layer(xr,  128, Wt0, bias0, h1, rowptr, esrc, dis, Ch, H0, H1, H2, H3, S0, S1, S2);
    cheb_layer(h1,   64, Wt1, bias1, h2, rowptr, esrc, dis, Ch, H0, H1, H2, H3, S0, S1, S2);
    cheb_layer(h2,   64, Wt2, bias2, h1, rowptr, esrc, dis, Ch, H0, H1, H2, H3, S0, S1, S2);

    // ---- mix head: dual-source GEMM (h1 | xr), fp32 output -> ChebConv K=2 -> out ----
    {
        dim3 grid((NN + 127) / 128, 1);
        gemm_mma<192, 64, 32, 64><<<grid, 256>>>(h1, xr, Wtm, biasm, dis, H0,
                                                 C, nullptr, 64, NN);
        int blocks = (NN * 16 + 255) / 256;
        clenshaw_prop<32><<<blocks, 256>>>(rowptr, esrc, H0, nullptr, 0, C, 64,
                                           nullptr, 0, nullptr, 0, dis,
                                           out, 32, nullptr, nullptr, -1.f, 0, 0, NN);
    }
}

// round 17
// speedup vs baseline: 1.0800x; 1.0332x over previous
#include <cuda_runtime.h>
#include <cuda_fp16.h>
#include <cstdint>

#define NN 100000
#define NE 3200000
#define NH 64

// ---------------- scratch (__device__ globals: allocation-free) ----------------
__device__ int    g_cnt[NN];
__device__ int    g_partial[512];
__device__ int    g_rowptr[NN + 1];
__device__ int    g_cursor[NN];
__device__ float  g_dis[NN];
__device__ int    g_esrc[NE];             // CSR-by-dst src indices (weights separable)
__device__ __half g_xh[(size_t)NN * 128]; // fp16 copy of x (GEMM A operand; fp16 mantissa == tf32)
__device__ float  g_C[(size_t)NN * 64];   // fp32 mix-head GEMM output
__device__ __half g_Ch[(size_t)NN * 448]; // fp16 fused layer-GEMM output: c_0..c_5 | skip
__device__ __half g_H0[NN * NH];          // pre-scaled (dis⊙) fp16 gather buffers
__device__ __half g_H1[NN * NH];
__device__ __half g_H2[NN * NH];
__device__ __half g_H3[NN * NH];
__device__ __half g_S0[NN * NH];          // fp16 Clenshaw b_k value buffers (sub operands)
__device__ __half g_S1[NN * NH];
__device__ __half g_S2[NN * NH];
__device__ __half g_h1[NN * NH];          // fp16 layer outputs (GEMM A operands)
__device__ __half g_h2[NN * NH];
// fp16 transposed weights (rows = output col, contiguous K) + fp32 fused bias vectors
__device__ __half g_Wt0[448 * 128];
__device__ __half g_Wt1[448 * 64];
__device__ __half g_Wt2[448 * 64];
__device__ __half g_Wtm[64 * 192];
__device__ float g_bias0[448];
__device__ float g_bias1[448];
__device__ float g_bias2[448];
__device__ float g_biasm[64];

__device__ __forceinline__ void mma_m16n8k8(float* c, uint32_t a0, uint32_t a1,
                                            uint32_t a2, uint32_t a3,
                                            uint32_t b0, uint32_t b1) {
    asm volatile(
        "mma.sync.aligned.m16n8k8.row.col.f32.tf32.tf32.f32 "
        "{%0,%1,%2,%3}, {%4,%5,%6,%7}, {%8,%9}, {%0,%1,%2,%3};"
        : "+f"(c[0]), "+f"(c[1]), "+f"(c[2]), "+f"(c[3])
        : "r"(a0), "r"(a1), "r"(a2), "r"(a3), "r"(b0), "r"(b1));
}

__device__ __forceinline__ void cp_async16(uint32_t saddr, const void* gptr, bool pred) {
    int sz = pred ? 16 : 0;
    asm volatile("cp.async.cg.shared.global [%0], [%1], 16, %2;\n"
                 :: "r"(saddr), "l"(gptr), "r"(sz));
}
#define CP_COMMIT() asm volatile("cp.async.commit_group;\n" ::: "memory")

// ---------------- graph preprocessing ----------------
__global__ void hist_kernel(const int* __restrict__ dst, int* __restrict__ cnt, int E) {
    int i = blockIdx.x * blockDim.x + threadIdx.x;
    if (i < E) atomicAdd(&cnt[dst[i]], 1);
}

__global__ void reduce_kernel(const int* __restrict__ cnt, int* __restrict__ partial, int n) {
    __shared__ int s[8];
    int i = blockIdx.x * 256 + threadIdx.x;
    int v = (i < n) ? cnt[i] : 0;
    #pragma unroll
    for (int o = 16; o; o >>= 1) v += __shfl_down_sync(0xffffffffu, v, o);
    if ((threadIdx.x & 31) == 0) s[threadIdx.x >> 5] = v;
    __syncthreads();
    if (threadIdx.x < 8) {
        int t = s[threadIdx.x];
        #pragma unroll
        for (int o = 4; o; o >>= 1) t += __shfl_down_sync(0xffu, t, o);
        if (threadIdx.x == 0) partial[blockIdx.x] = t;
    }
}

__global__ void scanp_kernel(int* __restrict__ partial, int nb, int* __restrict__ total_out) {
    __shared__ int ws[16];
    int tid = threadIdx.x, lane = tid & 31, w = tid >> 5;
    int v = (tid < nb) ? partial[tid] : 0;
    int x = v;
    #pragma unroll
    for (int o = 1; o < 32; o <<= 1) {
        int y = __shfl_up_sync(0xffffffffu, x, o);
        if (lane >= o) x += y;
    }
    if (lane == 31) ws[w] = x;
    __syncthreads();
    if (w == 0 && lane < 16) {
        int t = ws[lane];
        #pragma unroll
        for (int o = 1; o < 16; o <<= 1) {
            int y = __shfl_up_sync(0xffffu, t, o);
            if (lane >= o) t += y;
        }
        ws[lane] = t;
    }
    __syncthreads();
    int excl = x - v + (w ? ws[w - 1] : 0);
    if (tid < nb) partial[tid] = excl;
    if (tid == nb - 1) total_out[0] = excl + v;
}

// block-scan apply + fused dis = rsqrt(deg)
__global__ void apply_kernel(const int* __restrict__ cnt, const int* __restrict__ partial,
                             int* __restrict__ rowptr, int* __restrict__ cursor,
                             float* __restrict__ dis, int n) {
    __shared__ int ws[8];
    int i = blockIdx.x * 256 + threadIdx.x;
    int lane = threadIdx.x & 31, w = threadIdx.x >> 5;
    int v = (i < n) ? cnt[i] : 0;
    int x = v;
    #pragma unroll
    for (int o = 1; o < 32; o <<= 1) {
        int y = __shfl_up_sync(0xffffffffu, x, o);
        if (lane >= o) x += y;
    }
    if (lane == 31) ws[w] = x;
    __syncthreads();
    if (w == 0 && lane < 8) {
        int t = ws[lane];
        #pragma unroll
        for (int o = 1; o < 8; o <<= 1) {
            int y = __shfl_up_sync(0xffu, t, o);
            if (lane >= o) t += y;
        }
        ws[lane] = t;
    }
    __syncthreads();
    int excl = x - v + (w ? ws[w - 1] : 0) + partial[blockIdx.x];
    if (i < n) {
        rowptr[i] = excl;
        cursor[i] = excl;
        dis[i] = v > 0 ? rsqrtf((float)v) : 0.0f;
    }
}

__global__ void fill_kernel(const int* __restrict__ src, const int* __restrict__ dst,
                            int* __restrict__ cursor, int* __restrict__ esrc, int E) {
    int i = blockIdx.x * blockDim.x + threadIdx.x;
    if (i < E) {
        int d = dst[i];
        int pos = atomicAdd(&cursor[d], 1);
        esrc[pos] = src[i];
    }
}

// convert x to fp16 once (fp16 mantissa == tf32 mantissa for normal-range values)
__global__ void round_x(const float* __restrict__ x, __half* __restrict__ xh, int total4) {
    int i = blockIdx.x * blockDim.x + threadIdx.x;
    if (i < total4) {
        float4 v = ((const float4*)x)[i];
        __half2 h0 = __floats2half2_rn(v.x, v.y);
        __half2 h1 = __floats2half2_rn(v.z, v.w);
        ((uint2*)xh)[i] = make_uint2(*(uint32_t*)&h0, *(uint32_t*)&h1);
    }
}

// ---------------- weight prep: transpose to [OUT][KD], cvt to fp16; fused fp32 biases ----------------
__global__ void prep_weights(const float* __restrict__ W0, const float* __restrict__ Ws0,
                             const float* __restrict__ W1, const float* __restrict__ Ws1,
                             const float* __restrict__ W2, const float* __restrict__ Ws2,
                             const float* __restrict__ Wm,
                             const float* __restrict__ b0, const float* __restrict__ bs0,
                             const float* __restrict__ b1, const float* __restrict__ bs1,
                             const float* __restrict__ b2, const float* __restrict__ bs2,
                             const float* __restrict__ bm,
                             __half* __restrict__ Wt0, __half* __restrict__ Wt1,
                             __half* __restrict__ Wt2, __half* __restrict__ Wtm,
                             float* __restrict__ bias0, float* __restrict__ bias1,
                             float* __restrict__ bias2, float* __restrict__ biasm) {
    int idx = blockIdx.x * blockDim.x + threadIdx.x;
    const int S0 = 448 * 128, S1 = 448 * 64, S2 = 448 * 64, SM = 64 * 192;
    if (idx < S0) {
        int n = idx / 128, k = idx % 128;
        float v = (n < 384) ? W0[(size_t)(n / 64) * 128 * 64 + (size_t)k * 64 + (n % 64)]
                            : Ws0[(size_t)k * 64 + (n - 384)];
        Wt0[idx] = __float2half_rn(v);
        return;
    }
    idx -= S0;
    if (idx < S1) {
        int n = idx / 64, k = idx % 64;
        float v = (n < 384) ? W1[(size_t)(n / 64) * 64 * 64 + (size_t)k * 64 + (n % 64)]
                            : Ws1[(size_t)k * 64 + (n - 384)];
        Wt1[idx] = __float2half_rn(v);
        return;
    }
    idx -= S1;
    if (idx < S2) {
        int n = idx / 64, k = idx % 64;
        float v = (n < 384) ? W2[(size_t)(n / 64) * 64 * 64 + (size_t)k * 64 + (n % 64)]
                            : Ws2[(size_t)k * 64 + (n - 384)];
        Wt2[idx] = __float2half_rn(v);
        return;
    }
    idx -= S2;
    if (idx < SM) {
        int n = idx / 192, k = idx % 192;
        float v = (n < 32) ? Wm[(size_t)k * 32 + n]
                           : Wm[(size_t)192 * 32 + (size_t)k * 32 + (n - 32)];
        Wtm[idx] = __float2half_rn(v);
        return;
    }
    idx -= SM;
    if (idx < 448) { bias0[idx] = (idx < 64) ? b0[idx] : (idx >= 384 ? bs0[idx - 384] : 0.f); return; }
    idx -= 448;
    if (idx < 448) { bias1[idx] = (idx < 64) ? b1[idx] : (idx >= 384 ? bs1[idx - 384] : 0.f); return; }
    idx -= 448;
    if (idx < 448) { bias2[idx] = (idx < 64) ? b2[idx] : (idx >= 384 ? bs2[idx - 384] : 0.f); return; }
    idx -= 448;
    if (idx < 64) { biasm[idx] = (idx < 32) ? bm[idx] : 0.f; return; }
}

// ---------------- mma.sync tf32 GEMM (fp16 operands in smem; cp.async double buffer) ----------------
// A/A2/Wt are fp16; fragment loads convert fp16->fp32 (exact: fp16 mantissa fits tf32).
// LDA=40 halfs => 80B row stride (16B-aligned for cp.async).
template<int KD, int SPLIT, int WLO, int WHI>
__global__ __launch_bounds__(256)
void gemm_mma(const __half* __restrict__ A, const __half* __restrict__ A2,
              const __half* __restrict__ Wt, const float* __restrict__ biasfull,
              const float* __restrict__ dis, __half* __restrict__ Hout,
              float* __restrict__ C, __half* __restrict__ Chh, int OUT, int N) {
    constexpr int BM = 128, BN = 64, LDA = 40;   // LDA in halfs; 80B rows (16B-aligned)
    constexpr int NKT = KD / 32;
    constexpr int A2S = (KD > SPLIT) ? (KD - SPLIT) : 1;
    __shared__ __half As[2][BM * LDA];
    __shared__ __half Bs[2][BN * LDA];

    int tid = threadIdx.x;
    int lane = tid & 31, wid = tid >> 5;
    int wm = wid & 3, wn = wid >> 2;
    int quad = lane >> 2, qt = lane & 3;
    int br = blockIdx.x * BM;
    int colbase = blockIdx.y * BN;

    float acc[2][4][4];
    #pragma unroll
    for (int mi = 0; mi < 2; mi++)
        #pragma unroll
        for (int ni = 0; ni < 4; ni++)
            #pragma unroll
            for (int j = 0; j < 4; j++) acc[mi][ni][j] = 0.f;

    // A tile: 128x32 halfs = 512 16B-chunks (2/thread); B tile: 64x32 halfs = 256 (1/thread)
    int ar8[2], ac8[2];
    #pragma unroll
    for (int t = 0; t < 2; t++) {
        int i8 = tid + 256 * t;
        ar8[t] = i8 >> 2; ac8[t] = (i8 & 3) * 8;
    }
    int bn8 = tid >> 2, bc8 = (tid & 3) * 8;

    uint32_t sA[2], sB[2];
    sA[0] = (uint32_t)__cvta_generic_to_shared(As[0]);
    sA[1] = (uint32_t)__cvta_generic_to_shared(As[1]);
    sB[0] = (uint32_t)__cvta_generic_to_shared(Bs[0]);
    sB[1] = (uint32_t)__cvta_generic_to_shared(Bs[1]);

    auto issue = [&](int kt, int s) {
        int k0 = kt * 32;
        #pragma unroll
        for (int t = 0; t < 2; t++) {
            int gr = br + ar8[t];
            int col = k0 + ac8[t];
            const __half* srcp;
            if (SPLIT == KD || col < SPLIT) srcp = A + (size_t)gr * SPLIT + col;
            else                            srcp = A2 + (size_t)gr * A2S + (col - SPLIT);
            cp_async16(sA[s] + (ar8[t] * LDA + ac8[t]) * 2, srcp, gr < N);
        }
        cp_async16(sB[s] + (bn8 * LDA + bc8) * 2,
                   Wt + (size_t)(colbase + bn8) * KD + k0 + bc8, true);
        CP_COMMIT();
    };

    issue(0, 0);
    #pragma unroll
    for (int kt = 0; kt < NKT; kt++) {
        int s = kt & 1;
        if (kt + 1 < NKT) {
            issue(kt + 1, (kt + 1) & 1);
            asm volatile("cp.async.wait_group 1;\n" ::: "memory");
        } else {
            asm volatile("cp.async.wait_group 0;\n" ::: "memory");
        }
        __syncthreads();
        const __half* Ash = As[s];
        const __half* Bsh = Bs[s];
        #pragma unroll
        for (int ks = 0; ks < 4; ks++) {
            int kk = ks * 8;
            uint32_t a[2][4];
            #pragma unroll
            for (int mi = 0; mi < 2; mi++) {
                int row = wm * 32 + mi * 16 + quad;
                a[mi][0] = __float_as_uint(__half2float(Ash[row * LDA + kk + qt]));
                a[mi][1] = __float_as_uint(__half2float(Ash[(row + 8) * LDA + kk + qt]));
                a[mi][2] = __float_as_uint(__half2float(Ash[row * LDA + kk + qt + 4]));
                a[mi][3] = __float_as_uint(__half2float(Ash[(row + 8) * LDA + kk + qt + 4]));
            }
            #pragma unroll
            for (int ni = 0; ni < 4; ni++) {
                int col = wn * 32 + ni * 8 + quad;
                uint32_t b0 = __float_as_uint(__half2float(Bsh[col * LDA + kk + qt]));
                uint32_t b1 = __float_as_uint(__half2float(Bsh[col * LDA + kk + qt + 4]));
                #pragma unroll
                for (int mi = 0; mi < 2; mi++)
                    mma_m16n8k8(acc[mi][ni], a[mi][0], a[mi][1], a[mi][2], a[mi][3], b0, b1);
            }
        }
        __syncthreads();
    }
    #pragma unroll
    for (int mi = 0; mi < 2; mi++) {
        int r0 = br + wm * 32 + mi * 16 + quad;
        float d0 = 0.f, d1 = 0.f;
        if (WHI > WLO) {
            if (r0 < N) d0 = __ldg(dis + r0);
            if (r0 + 8 < N) d1 = __ldg(dis + r0 + 8);
        }
        #pragma unroll
        for (int ni = 0; ni < 4; ni++) {
            int cg = colbase + wn * 32 + ni * 8 + qt * 2;
            float bx = __ldg(biasfull + cg), by = __ldg(biasfull + cg + 1);
            float v0x = acc[mi][ni][0] + bx, v0y = acc[mi][ni][1] + by;
            float v1x = acc[mi][ni][2] + bx, v1y = acc[mi][ni][3] + by;
            bool inw = (WHI > WLO) && cg >= WLO && cg < WHI;
            if (r0 < N) {
                if (Chh)
                    *(__half2*)(Chh + (size_t)r0 * OUT + cg) = __floats2half2_rn(v0x, v0y);
                else
                    *(float2*)(C + (size_t)r0 * OUT + cg) = make_float2(v0x, v0y);
                if (inw)
                    ((__half2*)Hout)[(size_t)r0 * ((WHI - WLO) / 2) + (cg - WLO) / 2] =
                        __floats2half2_rn(d0 * v0x, d0 * v0y);
            }
            if (r0 + 8 < N) {
                if (Chh)
                    *(__half2*)(Chh + (size_t)(r0 + 8) * OUT + cg) = __floats2half2_rn(v1x, v1y);
                else
                    *(float2*)(C + (size_t)(r0 + 8) * OUT + cg) = make_float2(v1x, v1y);
                if (inw)
                    ((__half2*)Hout)[(size_t)(r0 + 8) * ((WHI - WLO) / 2) + (cg - WLO) / 2] =
                        __floats2half2_rn(d1 * v1x, d1 * v1y);
            }
        }
    }
}

// ---------------- Clenshaw propagation (R8 loop body; fp16/fp32 operand variants) ----------------
// v = scale*dis[d]*sum(gather fp16) + (addh|addf) - (subh); relu?; + skiph
// outputs: out fp32 (opt) | outs fp16 of v (opt) | outh fp16 of dis*v (opt)
template<int F>
__global__ __launch_bounds__(256)
void clenshaw_prop(const int* __restrict__ rowptr, const int* __restrict__ esrc,
                   const __half* __restrict__ tin_h,
                   const __half* __restrict__ addh, int ah_s,
                   const float* __restrict__ addf, int af_s,
                   const __half* __restrict__ subh, int sh_s,
                   const __half* __restrict__ skiph, int kh_s,
                   const float* __restrict__ dis,
                   float* __restrict__ out, int out_stride,
                   __half* __restrict__ outs, __half* __restrict__ outh,
                   float scale, int do_relu, int n) {
    constexpr int L = F / 2;
    int gt = blockIdx.x * blockDim.x + threadIdx.x;
    int node = gt / L;
    if (node >= n) return;
    int sl = gt & (L - 1);
    int beg = __ldg(rowptr + node), end = __ldg(rowptr + node + 1);
    const __half2* tin2 = (const __half2*)tin_h;
    float2 a0 = make_float2(0.f, 0.f), a1 = make_float2(0.f, 0.f);
    float2 a2 = make_float2(0.f, 0.f), a3 = make_float2(0.f, 0.f);
    int p = beg;
    for (; p + 8 <= end; p += 8) {
        int s0 = __ldg(esrc + p),     s1 = __ldg(esrc + p + 1);
        int s2 = __ldg(esrc + p + 2), s3 = __ldg(esrc + p + 3);
        int s4 = __ldg(esrc + p + 4), s5 = __ldg(esrc + p + 5);
        int s6 = __ldg(esrc + p + 6), s7 = __ldg(esrc + p + 7);
        float2 f0 = __half22float2(__ldg(tin2 + (size_t)s0 * L + sl));
        float2 f1 = __half22float2(__ldg(tin2 + (size_t)s1 * L + sl));
        float2 f2 = __half22float2(__ldg(tin2 + (size_t)s2 * L + sl));
        float2 f3 = __half22float2(__ldg(tin2 + (size_t)s3 * L + sl));
        float2 f4 = __half22float2(__ldg(tin2 + (size_t)s4 * L + sl));
        float2 f5 = __half22float2(__ldg(tin2 + (size_t)s5 * L + sl));
        float2 f6 = __half22float2(__ldg(tin2 + (size_t)s6 * L + sl));
        float2 f7 = __half22float2(__ldg(tin2 + (size_t)s7 * L + sl));
        a0.x += f0.x + f4.x; a0.y += f0.y + f4.y;
        a1.x += f1.x + f5.x; a1.y += f1.y + f5.y;
        a2.x += f2.x + f6.x; a2.y += f2.y + f6.y;
        a3.x += f3.x + f7.x; a3.y += f3.y + f7.y;
    }
    for (; p < end; ++p) {
        int s = __ldg(esrc + p);
        float2 f = __half22float2(__ldg(tin2 + (size_t)s * L + sl));
        a0.x += f.x; a0.y += f.y;
    }
    float d = __ldg(dis + node);
    float sd = scale * d;
    float vx = sd * ((a0.x + a1.x) + (a2.x + a3.x));
    float vy = sd * ((a0.y + a1.y) + (a2.y + a3.y));
    if (addh) {
        float2 ad = __half22float2(*(const __half2*)(addh + (size_t)node * ah_s + 2 * sl));
        vx += ad.x; vy += ad.y;
    } else {
        float2 ad = ((const float2*)(addf + (size_t)node * af_s))[sl];
        vx += ad.x; vy += ad.y;
    }
    if (subh) {
        float2 s = __half22float2(*(const __half2*)(subh + (size_t)node * sh_s + 2 * sl));
        vx -= s.x; vy -= s.y;
    }
    if (do_relu) { vx = fmaxf(vx, 0.f); vy = fmaxf(vy, 0.f); }
    if (skiph) {
        float2 s = __half22float2(*(const __half2*)(skiph + (size_t)node * kh_s + 2 * sl));
        vx += s.x; vy += s.y;
    }
    if (out)
        ((float2*)(out + (size_t)node * out_stride))[sl] = make_float2(vx, vy);
    if (outs)
        ((__half2*)outs)[(size_t)node * L + sl] = __floats2half2_rn(vx, vy);
    if (outh)
        ((__half2*)outh)[(size_t)node * L + sl] = __floats2half2_rn(d * vx, d * vy);
}

// ---------------- host orchestration ----------------
static void prop64(const int* rowptr, const int* esrc, const __half* tin_h,
                   const __half* addh, int ah_s,
                   const __half* subh, int sh_s,
                   const __half* skiph, int kh_s,
                   const float* dis,
                   float* out, int os, __half* outs, __half* outh,
                   float scale, int relu) {
    int blocks = (NN * 32 + 255) / 256;
    clenshaw_prop<64><<<blocks, 256>>>(rowptr, esrc, tin_h, addh, ah_s, nullptr, 0,
                                       subh, sh_s, skiph, kh_s, dis,
                                       out, os, outs, outh, scale, relu, NN);
}

static void cheb_layer(const __half* h, int kd,
                       const __half* Wt, const float* biasfull,
                       __half* hout, const int* rowptr, const int* esrc,
                       const float* dis, __half* Ch,
                       __half* H0, __half* H1, __half* H2, __half* H3,
                       __half* S0, __half* S1, __half* S2) {
    dim3 grid((NN + 127) / 128, 7);
    if (kd == 128)
        gemm_mma<128, 128, 320, 384><<<grid, 256>>>(h, nullptr, Wt, biasfull, dis, H3,
                                                    nullptr, Ch, 448, NN);
    else
        gemm_mma<64, 64, 320, 384><<<grid, 256>>>(h, nullptr, Wt, biasfull, dis, H3,
                                                  nullptr, Ch, 448, NN);
    // b4 = c4 + 2L b5                       -> S0 (fp16 value), H0 (gather)
    prop64(rowptr, esrc, H3, Ch + 4 * 64, 448, nullptr, 0, nullptr, 0,
           dis, nullptr, 0, S0, H0, -2.f, 0);
    // b3 = c3 + 2L b4 - c5 (fp16 from Ch)   -> S1, H1
    prop64(rowptr, esrc, H0, Ch + 3 * 64, 448, Ch + 5 * 64, 448, nullptr, 0,
           dis, nullptr, 0, S1, H1, -2.f, 0);
    // b2 = c2 + 2L b3 - b4 (S0)             -> S2, H2
    prop64(rowptr, esrc, H1, Ch + 2 * 64, 448, S0, 64, nullptr, 0,
           dis, nullptr, 0, S2, H2, -2.f, 0);
    // b1 = c1 + 2L b2 - b3 (S1)             -> H0 only
    prop64(rowptr, esrc, H2, Ch + 1 * 64, 448, S1, 64, nullptr, 0,
           dis, nullptr, 0, nullptr, H0, -2.f, 0);
    // h = relu(c0 + L b1 - b2 (S2)) + skip (fp16 Ch+384) -> hout fp16 (GEMM A operand)
    prop64(rowptr, esrc, H0, Ch, 448, S2, 64, Ch + 6 * 64, 448,
           dis, nullptr, 0, hout, nullptr, -1.f, 1);
}

extern "C" void kernel_launch(void* const* d_in, const int* in_sizes, int n_in,
                              void* d_out, int out_size) {
    const float* x   = (const float*)d_in[0];
    const int*   ei  = (const int*)d_in[1];
    const float* W0  = (const float*)d_in[2];
    const float* b0  = (const float*)d_in[3];
    const float* Ws0 = (const float*)d_in[4];
    const float* bs0 = (const float*)d_in[5];
    const float* W1  = (const float*)d_in[6];
    const float* b1  = (const float*)d_in[7];
    const float* Ws1 = (const float*)d_in[8];
    const float* bs1 = (const float*)d_in[9];
    const float* W2  = (const float*)d_in[10];
    const float* b2  = (const float*)d_in[11];
    const float* Ws2 = (const float*)d_in[12];
    const float* bs2 = (const float*)d_in[13];
    const float* Wm  = (const float*)d_in[14];
    const float* bm  = (const float*)d_in[15];
    float* out = (float*)d_out;

    const int* src = ei;
    const int* dst = ei + NE;

    void* p;
    cudaGetSymbolAddress(&p, g_cnt);     int*    cnt     = (int*)p;
    cudaGetSymbolAddress(&p, g_partial); int*    partial = (int*)p;
    cudaGetSymbolAddress(&p, g_rowptr);  int*    rowptr  = (int*)p;
    cudaGetSymbolAddress(&p, g_cursor);  int*    cursor  = (int*)p;
    cudaGetSymbolAddress(&p, g_dis);     float*  dis     = (float*)p;
    cudaGetSymbolAddress(&p, g_esrc);    int*    esrc    = (int*)p;
    cudaGetSymbolAddress(&p, g_xh);      __half* xh      = (__half*)p;
    cudaGetSymbolAddress(&p, g_C);       float*  C       = (float*)p;
    cudaGetSymbolAddress(&p, g_Ch);      __half* Ch      = (__half*)p;
    cudaGetSymbolAddress(&p, g_H0);      __half* H0      = (__half*)p;
    cudaGetSymbolAddress(&p, g_H1);      __half* H1      = (__half*)p;
    cudaGetSymbolAddress(&p, g_H2);      __half* H2      = (__half*)p;
    cudaGetSymbolAddress(&p, g_H3);      __half* H3      = (__half*)p;
    cudaGetSymbolAddress(&p, g_S0);      __half* S0      = (__half*)p;
    cudaGetSymbolAddress(&p, g_S1);      __half* S1      = (__half*)p;
    cudaGetSymbolAddress(&p, g_S2);      __half* S2      = (__half*)p;
    cudaGetSymbolAddress(&p, g_h1);      __half* h1      = (__half*)p;
    cudaGetSymbolAddress(&p, g_h2);      __half* h2      = (__half*)p;
    cudaGetSymbolAddress(&p, g_Wt0);     __half* Wt0     = (__half*)p;
    cudaGetSymbolAddress(&p, g_Wt1);     __half* Wt1     = (__half*)p;
    cudaGetSymbolAddress(&p, g_Wt2);     __half* Wt2     = (__half*)p;
    cudaGetSymbolAddress(&p, g_Wtm);     __half* Wtm     = (__half*)p;
    cudaGetSymbolAddress(&p, g_bias0);   float*  bias0   = (float*)p;
    cudaGetSymbolAddress(&p, g_bias1);   float*  bias1   = (float*)p;
    cudaGetSymbolAddress(&p, g_bias2);   float*  bias2   = (float*)p;
    cudaGetSymbolAddress(&p, g_biasm);   float*  biasm   = (float*)p;

    // ---- weight prep + x conversion ----
    {
        int total = 448 * 128 + 448 * 64 + 448 * 64 + 64 * 192 + 448 * 3 + 64;
        prep_weights<<<(total + 255) / 256, 256>>>(W0, Ws0, W1, Ws1, W2, Ws2, Wm,
                                                   b0, bs0, b1, bs1, b2, bs2, bm,
                                                   Wt0, Wt1, Wt2, Wtm,
                                                   bias0, bias1, bias2, biasm);
        round_x<<<(NN * 32 + 255) / 256, 256>>>(x, xh, NN * 32);
    }

    // ---- preprocessing: degree + dis, CSR (sorted by dst) ----
    cudaMemsetAsync(cnt, 0, NN * sizeof(int), 0);
    hist_kernel<<<(NE + 255) / 256, 256>>>(dst, cnt, NE);
    int nb = (NN + 255) / 256;
    reduce_kernel<<<nb, 256>>>(cnt, partial, NN);
    scanp_kernel<<<1, 512>>>(partial, nb, rowptr + NN);
    apply_kernel<<<nb, 256>>>(cnt, partial, rowptr, cursor, dis, NN);
    fill_kernel<<<(NE + 255) / 256, 256>>>(src, dst, cursor, esrc, NE);

    // ---- 3 Kipf blocks (Clenshaw, fp16 storage everywhere; fp32 accumulation) ----
    cheb_layer(xh,  128, Wt0, bias0, h1, rowptr, esrc, dis, Ch, H0, H1, H2, H3, S0, S1, S2);
    cheb_layer(h1,   64, Wt1, bias1, h2, rowptr, esrc, dis, Ch, H0, H1, H2, H3, S0, S1, S2);
    cheb_layer(h2,   64, Wt2, bias2, h1, rowptr, esrc, dis, Ch, H0, H1, H2, H3, S0, S1, S2);

    // ---- mix head: dual-source GEMM (h1 | xh), fp32 output -> ChebConv K=2 -> out ----
    {
        dim3 grid((NN + 127) / 128, 1);
        gemm_mma<192, 64, 32, 64><<<grid, 256>>>(h1, xh, Wtm, biasm, dis, H0,
                                                 C, nullptr, 64, NN);
        int blocks = (NN * 16 + 255) / 256;
        clenshaw_prop<32><<<blocks, 256>>>(rowptr, esrc, H0, nullptr, 0, C, 64,
                                           nullptr, 0, nullptr, 0, dis,
                                           out, 32, nullptr, nullptr, -1.f, 0, NN);
    }
}